// round 5
// baseline (speedup 1.0000x reference)
#include <cuda_runtime.h>
#include <cstdint>
#include <math.h>

#define Bv   32
#define Pv   196
#define ENCv 2048
#define DECv 512
#define EMBv 512
#define ATTv 512
#define Vv   32000
#define Lv   21
#define Tv   20
#define KSv  8
#define NBv  128
#define NTv  256
#define SMEM_BYTES 66560

// ---------------- scratch ----------------
__device__ float g_att1 [(size_t)Bv * Pv * ATTv];   // 12.8 MB (sorted order)
__device__ float g_mean [Bv * ENCv];
__device__ float g_h    [Bv * DECv];
__device__ float g_c    [Bv * DECv];
__device__ float g_att2 [Bv * ATTv];
__device__ float g_gate [Bv * ENCv];
__device__ float g_e    [Bv * Pv];
__device__ float g_xh   [Bv * 3072];
__device__ float g_hall [(size_t)Tv * Bv * DECv];
__device__ float g_paw  [(size_t)NBv * ENCv];       // partial awe
__device__ float2 g_pms [NBv];                      // partial (max, sumexp)
__device__ float g_part [(size_t)16 * Bv * 2048];   // LSTM split-K partials
__device__ float g_partA[(size_t)KSv * Bv * 2560];  // h0/c0 partials
__device__ int   g_sort  [Bv];
__device__ int   g_declen[Bv];

// ---------------- grid barrier (2-level, generation counter) ----------------
__device__ unsigned g_cnt0[8];
__device__ unsigned g_cnt1;
__device__ volatile unsigned g_gen;

__device__ __forceinline__ void gbar()
{
    __syncthreads();
    __threadfence();
    if (threadIdx.x == 0) {
        unsigned gen = g_gen;
        int grp = blockIdx.x >> 4;
        if (atomicInc(&g_cnt0[grp], 15u) == 15u) {
            if (atomicInc(&g_cnt1, 7u) == 7u) {
                __threadfence();
                g_gen = gen + 1;
            }
        }
        while (g_gen == gen) __nanosleep(64);
    }
    __syncthreads();
    __threadfence();
}

__device__ __forceinline__ float sigmf(float x){ return 1.0f / (1.0f + expf(-x)); }

// ---------------- setup kernels ----------------
__global__ void k_sort(const int* __restrict__ lens)
{
    __shared__ int s[Bv];
    int b = threadIdx.x;
    s[b] = lens[b];
    __syncthreads();
    int my = s[b], rank = 0;
    for (int j = 0; j < Bv; j++) {
        int lj = s[j];
        rank += (lj > my) || (lj == my && j < b);
    }
    g_sort[rank]   = b;
    g_declen[rank] = my - 1;
}

__global__ void k_mean(const float* __restrict__ enc)
{
    int b = blockIdx.x;
    int e = blockIdx.y * 256 + threadIdx.x;
    int src = g_sort[b];
    const float* in = enc + (size_t)src * Pv * ENCv + e;
    float s = 0.f;
    #pragma unroll 4
    for (int p = 0; p < Pv; p++) s += in[(size_t)p * ENCv];
    g_mean[b * ENCv + e] = s * (1.0f / (float)Pv);
}

// ---------------- big SGEMM: C[m,n] = sum_k A[m,k]*W[n,k] + bias[n] ----------------
// mode 0: plain store.  mode 1: preds scatter epilogue.  mode 2: plain store + indirect A rows.
__global__ void __launch_bounds__(256) k_bgemm(
    const float* __restrict__ A, const float* __restrict__ W,
    const float* __restrict__ bias, float* __restrict__ C,
    int M, int N, int K, int mode)
{
    __shared__ float As[8][128];
    __shared__ float Ws[8][128];
    int tid = threadIdx.x;
    int m0 = blockIdx.y * 128, n0 = blockIdx.x * 128;
    int lr = tid >> 1, lc = (tid & 1) * 4;
    int ar = m0 + lr;
    if (mode == 2) ar = g_sort[ar / Pv] * Pv + (ar % Pv);
    const float* Ap = A + (size_t)ar * K + lc;
    const float* Wp = W + (size_t)(n0 + lr) * K + lc;
    int ty = tid >> 4, tx = tid & 15;

    float acc[8][8];
    #pragma unroll
    for (int i = 0; i < 8; i++)
        #pragma unroll
        for (int j = 0; j < 8; j++) acc[i][j] = 0.f;

    float4 av = *(const float4*)(Ap);
    float4 wv = *(const float4*)(Wp);

    for (int k0 = 0; k0 < K; k0 += 8) {
        __syncthreads();
        As[lc+0][lr]=av.x; As[lc+1][lr]=av.y; As[lc+2][lr]=av.z; As[lc+3][lr]=av.w;
        Ws[lc+0][lr]=wv.x; Ws[lc+1][lr]=wv.y; Ws[lc+2][lr]=wv.z; Ws[lc+3][lr]=wv.w;
        __syncthreads();
        if (k0 + 8 < K) {
            av = *(const float4*)(Ap + k0 + 8);
            wv = *(const float4*)(Wp + k0 + 8);
        }
        #pragma unroll
        for (int k = 0; k < 8; k++) {
            float a[8], w[8];
            *(float4*)(a)     = *(const float4*)&As[k][ty*4];
            *(float4*)(a + 4) = *(const float4*)&As[k][64 + ty*4];
            *(float4*)(w)     = *(const float4*)&Ws[k][tx*4];
            *(float4*)(w + 4) = *(const float4*)&Ws[k][64 + tx*4];
            #pragma unroll
            for (int i = 0; i < 8; i++)
                #pragma unroll
                for (int j = 0; j < 8; j++)
                    acc[i][j] = fmaf(a[i], w[j], acc[i][j]);
        }
    }

    #pragma unroll
    for (int i = 0; i < 8; i++) {
        int m = m0 + ty*4 + (i & 3) + (i >> 2) * 64;
        #pragma unroll
        for (int j = 0; j < 8; j++) {
            int n = n0 + tx*4 + (j & 3) + (j >> 2) * 64;
            float v = acc[i][j] + bias[n];
            if (mode == 1) {
                int t = m >> 5, b = m & 31;
                C[(size_t)b * ((size_t)Tv * Vv) + (size_t)t * Vv + n] =
                    (t < g_declen[b]) ? v : 0.f;
            } else {
                C[(size_t)m * N + n] = v;
            }
        }
    }
}

// ---------------- small-M split-K GEMM (h0/c0 only) ----------------
__global__ void __launch_bounds__(256) k_sgemm(
    const float* __restrict__ A, int K, int N,
    const float* __restrict__ W1, float* __restrict__ part)
{
    __shared__ float As[16][32];
    __shared__ float Ws[16][128];
    int tid = threadIdx.x;
    int Kc = K / KSv;
    int kbase = blockIdx.y * Kc;
    int n0 = blockIdx.x * 128;
    int tym = tid >> 5, txn = tid & 31;

    float acc[4][4];
    #pragma unroll
    for (int i = 0; i < 4; i++)
        #pragma unroll
        for (int j = 0; j < 4; j++) acc[i][j] = 0.f;

    float4 ra = make_float4(0.f,0.f,0.f,0.f);
    int am = tid >> 2, ac4 = (tid & 3) * 4;
    if (tid < 128) ra = *(const float4*)(A + (size_t)am * K + kbase + ac4);
    int n1 = n0 + (tid >> 2),           kc41 = (tid & 3) * 4;
    int n2 = n0 + ((tid + 256) >> 2),   kc42 = ((tid + 256) & 3) * 4;
    float4 rw0 = *(const float4*)(W1 + (size_t)n1 * K + kbase + kc41);
    float4 rw1 = *(const float4*)(W1 + (size_t)n2 * K + kbase + kc42);

    for (int kb = 0; kb < Kc; kb += 16) {
        __syncthreads();
        if (tid < 128) {
            As[ac4+0][am]=ra.x; As[ac4+1][am]=ra.y; As[ac4+2][am]=ra.z; As[ac4+3][am]=ra.w;
        }
        {
            int nr0 = tid >> 2;
            Ws[kc41+0][nr0]=rw0.x; Ws[kc41+1][nr0]=rw0.y; Ws[kc41+2][nr0]=rw0.z; Ws[kc41+3][nr0]=rw0.w;
            int nr1 = (tid + 256) >> 2;
            Ws[kc42+0][nr1]=rw1.x; Ws[kc42+1][nr1]=rw1.y; Ws[kc42+2][nr1]=rw1.z; Ws[kc42+3][nr1]=rw1.w;
        }
        __syncthreads();
        if (kb + 16 < Kc) {
            int kn = kbase + kb + 16;
            if (tid < 128) ra = *(const float4*)(A + (size_t)am * K + kn + ac4);
            rw0 = *(const float4*)(W1 + (size_t)n1 * K + kn + kc41);
            rw1 = *(const float4*)(W1 + (size_t)n2 * K + kn + kc42);
        }
        #pragma unroll
        for (int k = 0; k < 16; k++) {
            float a[4], w[4];
            *(float4*)a = *(const float4*)&As[k][tym*4];
            *(float4*)w = *(const float4*)&Ws[k][txn*4];
            #pragma unroll
            for (int i = 0; i < 4; i++)
                #pragma unroll
                for (int j = 0; j < 4; j++)
                    acc[i][j] = fmaf(a[i], w[j], acc[i][j]);
        }
    }

    float* pp = part + (size_t)blockIdx.y * Bv * N;
    #pragma unroll
    for (int i = 0; i < 4; i++) {
        int m = tym*4 + i;
        #pragma unroll
        for (int j = 0; j < 4; j++)
            pp[(size_t)m * N + n0 + txn*4 + j] = acc[i][j];
    }
}

__global__ void k_red(float* __restrict__ dest, const float* __restrict__ bias, int N)
{
    int idx = blockIdx.x * 256 + threadIdx.x;
    int b = idx / N, n = idx - b * N;
    float s = bias[n];
    #pragma unroll
    for (int ks = 0; ks < KSv; ks++) s += g_partA[((size_t)ks * Bv + b) * N + n];
    dest[idx] = s;
}

// ================= persistent step kernel =================
__global__ void __launch_bounds__(256) k_steps(
    const float* __restrict__ enc, const int* __restrict__ caps,
    const float* __restrict__ embW,
    const float* __restrict__ W_da, const float* __restrict__ b_da,
    const float* __restrict__ W_fb, const float* __restrict__ b_fb,
    const float* __restrict__ w_fa,
    const float* __restrict__ W_ih, const float* __restrict__ b_ih,
    const float* __restrict__ W_hh, const float* __restrict__ b_hh,
    float* __restrict__ out_alpha)
{
    extern __shared__ float smf[];
    const int blk = blockIdx.x, tid = threadIdx.x;
    const int wid = tid >> 5, lane = tid & 31;

    for (int t = 0; t < Tv; t++) {
        // ---------- S1a: att2 (N=512) + gate (N=2048) warp-dots, h in smem ----------
        {
            float4* sh4 = (float4*)smf;
            const float4* hg = (const float4*)g_h;
            for (int i = tid; i < (Bv * DECv) / 4; i += NTv) sh4[i] = __ldcg(hg + i);
            __syncthreads();
            int nbase = blk * 20;
            for (int d = wid; d < 20 * Bv; d += 8) {
                int nl = d >> 5, b = d & 31;
                int n = nbase + nl;
                const float4* wr4 = (n < 512)
                    ? (const float4*)(W_da + (size_t)n * 512)
                    : (const float4*)(W_fb + (size_t)(n - 512) * 512);
                const float4* h4 = (const float4*)(smf + b * 512);
                float acc = 0.f;
                #pragma unroll
                for (int i = 0; i < 4; i++) {
                    float4 wv = __ldg(wr4 + lane * 4 + i);
                    float4 hv = h4[lane * 4 + i];
                    acc += wv.x*hv.x + wv.y*hv.y + wv.z*hv.z + wv.w*hv.w;
                }
                #pragma unroll
                for (int off = 16; off; off >>= 1) acc += __shfl_xor_sync(0xffffffffu, acc, off);
                if (lane == 0) {
                    if (n < 512) g_att2[b * 512 + n] = acc + __ldg(b_da + n);
                    else         g_gate[b * 2048 + (n - 512)] = sigmf(acc + __ldg(b_fb + (n - 512)));
                }
            }
        }
        gbar();

        // ---------- S1b: e + local softmax stats + partial awe ----------
        {
            int b = blk >> 2, q = blk & 3, p0 = q * 49;
            int srcb = g_sort[b];
            float* satt2 = smf;
            float* swfa  = smf + 512;
            float* se    = smf + 1024;
            float* swe   = smf + 1088;
            float* sred  = smf + 1152;
            const float4* a2g = (const float4*)(g_att2 + b * 512);
            const float4* wfg = (const float4*)w_fa;
            for (int i = tid; i < 128; i += NTv) {
                ((float4*)satt2)[i] = __ldcg(a2g + i);
                ((float4*)swfa)[i]  = __ldg(wfg + i);
            }
            __syncthreads();
            for (int d = wid; d < 49; d += 8) {
                const float4* a1 = (const float4*)(g_att1 + ((size_t)(b * Pv + p0 + d)) * 512);
                float acc = 0.f;
                #pragma unroll
                for (int i = 0; i < 4; i++) {
                    float4 av = __ldg(a1 + lane * 4 + i);
                    float4 t2 = ((const float4*)satt2)[lane * 4 + i];
                    float4 wf = ((const float4*)swfa)[lane * 4 + i];
                    acc += fmaxf(av.x + t2.x, 0.f) * wf.x + fmaxf(av.y + t2.y, 0.f) * wf.y
                         + fmaxf(av.z + t2.z, 0.f) * wf.z + fmaxf(av.w + t2.w, 0.f) * wf.w;
                }
                #pragma unroll
                for (int off = 16; off; off >>= 1) acc += __shfl_xor_sync(0xffffffffu, acc, off);
                if (lane == 0) { se[d] = acc; g_e[b * Pv + p0 + d] = acc; }
            }
            __syncthreads();
            if (tid == 0) {
                float m = -3.4e38f;
                for (int i = 0; i < 49; i++) m = fmaxf(m, se[i]);
                sred[0] = m;
            }
            __syncthreads();
            float m = sred[0];
            if (tid < 49) swe[tid] = expf(se[tid] - m);
            __syncthreads();
            if (tid == 0) {
                float s = 0.f;
                for (int i = 0; i < 49; i++) s += swe[i];
                g_pms[blk] = make_float2(m, s);
            }
            float4 acc0 = make_float4(0.f,0.f,0.f,0.f);
            float4 acc1 = make_float4(0.f,0.f,0.f,0.f);
            for (int p = 0; p < 49; p++) {
                float w = swe[p];
                const float4* er = (const float4*)(enc + ((size_t)srcb * Pv + p0 + p) * ENCv);
                float4 v0 = __ldg(er + tid);
                float4 v1 = __ldg(er + tid + 256);
                acc0.x = fmaf(w, v0.x, acc0.x); acc0.y = fmaf(w, v0.y, acc0.y);
                acc0.z = fmaf(w, v0.z, acc0.z); acc0.w = fmaf(w, v0.w, acc0.w);
                acc1.x = fmaf(w, v1.x, acc1.x); acc1.y = fmaf(w, v1.y, acc1.y);
                acc1.z = fmaf(w, v1.z, acc1.z); acc1.w = fmaf(w, v1.w, acc1.w);
            }
            float4* pw = (float4*)(g_paw + (size_t)blk * ENCv);
            pw[tid]       = acc0;
            pw[tid + 256] = acc1;
        }
        gbar();

        // ---------- S1c: combine awe, build xh, write alphas ----------
        {
            int b = blk >> 2, q = blk & 3;
            float2 ms[4];
            float M = -3.4e38f;
            #pragma unroll
            for (int j = 0; j < 4; j++) { ms[j] = __ldcg(&g_pms[b * 4 + j]); M = fmaxf(M, ms[j].x); }
            float Z = 0.f;
            #pragma unroll
            for (int j = 0; j < 4; j++) Z += ms[j].y * expf(ms[j].x - M);
            float invZ = 1.0f / Z;
            float coef[4];
            #pragma unroll
            for (int j = 0; j < 4; j++) coef[j] = expf(ms[j].x - M) * invZ;

            int e0 = q * 512;
            for (int i = tid; i < 512; i += NTv) {
                int e = e0 + i;
                float a = 0.f;
                #pragma unroll
                for (int j = 0; j < 4; j++)
                    a = fmaf(coef[j], __ldcg(g_paw + (size_t)(b * 4 + j) * ENCv + e), a);
                g_xh[b * 3072 + 512 + e] = __ldcg(g_gate + b * 2048 + e) * a;
            }
            int dl = g_declen[b];
            if (q == 0) {
                int cap = caps[g_sort[b] * Lv + t];
                for (int i = tid; i < 512; i += NTv)
                    g_xh[b * 3072 + i] = __ldg(embW + (size_t)cap * EMBv + i);
            } else if (q == 1) {
                for (int i = tid; i < 512; i += NTv)
                    g_xh[b * 3072 + 2560 + i] = __ldcg(g_h + b * 512 + i);
            } else {
                int pp0 = (q - 2) * 98;
                for (int i = tid; i < 98; i += NTv) {
                    int p = pp0 + i;
                    float al = (t < dl) ? expf(__ldcg(g_e + b * Pv + p) - M) * invZ : 0.f;
                    out_alpha[((size_t)b * Tv + t) * Pv + p] = al;
                }
            }
        }
        gbar();

        // ---------- S3: LSTM GEMM partials (8 n-chunks x 16 k-splits) ----------
        {
            float* sa = smf;          // 32 x 36
            float* sw = smf + 1152;   // 32 x 260
            int nc = blk & 7, ks = blk >> 3;
            int n0 = nc * 256, k0 = ks * 192;
            int bg = tid >> 6, nt = tid & 63;
            int b0 = bg * 8;
            float acc[8][4];
            #pragma unroll
            for (int i = 0; i < 8; i++)
                #pragma unroll
                for (int j = 0; j < 4; j++) acc[i][j] = 0.f;

            for (int su = 0; su < 6; su++) {
                int kb = k0 + su * 32;
                #pragma unroll
                for (int i = 0; i < 4; i++) {
                    int b = (tid >> 5) + i * 8, k = tid & 31;
                    sa[k * 36 + b] = __ldcg(g_xh + b * 3072 + kb + k);
                }
                #pragma unroll
                for (int i = 0; i < 8; i++) {
                    int n = (tid >> 3) + i * 32;
                    int kq = (tid & 7) * 4;
                    int gn = n0 + n, k = kb + kq;
                    const float* src = (k < 2560) ? (W_ih + (size_t)gn * 2560 + k)
                                                  : (W_hh + (size_t)gn * 512 + (k - 2560));
                    float4 w = __ldg((const float4*)src);
                    sw[(kq + 0) * 260 + n] = w.x;
                    sw[(kq + 1) * 260 + n] = w.y;
                    sw[(kq + 2) * 260 + n] = w.z;
                    sw[(kq + 3) * 260 + n] = w.w;
                }
                __syncthreads();
                #pragma unroll
                for (int k = 0; k < 32; k++) {
                    float4 a0 = *(const float4*)(sa + k * 36 + b0);
                    float4 a1 = *(const float4*)(sa + k * 36 + b0 + 4);
                    float4 wv = *(const float4*)(sw + k * 260 + nt * 4);
                    float ar[8] = {a0.x, a0.y, a0.z, a0.w, a1.x, a1.y, a1.z, a1.w};
                    float wr[4] = {wv.x, wv.y, wv.z, wv.w};
                    #pragma unroll
                    for (int i = 0; i < 8; i++)
                        #pragma unroll
                        for (int j = 0; j < 4; j++)
                            acc[i][j] = fmaf(ar[i], wr[j], acc[i][j]);
                }
                __syncthreads();
            }
            #pragma unroll
            for (int i = 0; i < 8; i++) {
                float4 v = make_float4(acc[i][0], acc[i][1], acc[i][2], acc[i][3]);
                *(float4*)(g_part + ((size_t)(ks * 32 + b0 + i)) * 2048 + n0 + nt * 4) = v;
            }
        }
        gbar();

        // ---------- S4: reduce + LSTM pointwise + state update ----------
        {
            if (tid < 128) {
                int idx = blk * 128 + tid;
                int b = idx >> 9, j = idx & 511;
                float gi = __ldg(b_ih + j)        + __ldg(b_hh + j);
                float gf = __ldg(b_ih + 512 + j)  + __ldg(b_hh + 512 + j);
                float gg = __ldg(b_ih + 1024 + j) + __ldg(b_hh + 1024 + j);
                float go = __ldg(b_ih + 1536 + j) + __ldg(b_hh + 1536 + j);
                #pragma unroll
                for (int ks = 0; ks < 16; ks++) {
                    const float* pp = g_part + ((size_t)(ks * 32 + b)) * 2048;
                    gi += __ldcg(pp + j);        gf += __ldcg(pp + 512 + j);
                    gg += __ldcg(pp + 1024 + j); go += __ldcg(pp + 1536 + j);
                }
                float cn = sigmf(gf) * __ldcg(g_c + b * 512 + j) + sigmf(gi) * tanhf(gg);
                float hn = sigmf(go) * tanhf(cn);
                g_hall[((size_t)t * Bv + b) * DECv + j] = hn;
                if (t < g_declen[b]) { g_h[b * 512 + j] = hn; g_c[b * 512 + j] = cn; }
            }
        }
        gbar();
    }
}

// ---------------- host launcher ----------------
extern "C" void kernel_launch(void* const* d_in, const int* in_sizes, int n_in,
                              void* d_out, int out_size)
{
    const float* enc  = (const float*)d_in[0];
    const int*   caps = (const int*)  d_in[1];
    const int*   lens = (const int*)  d_in[2];
    const float* embW = (const float*)d_in[3];
    const float* W_ea = (const float*)d_in[4];
    const float* b_ea = (const float*)d_in[5];
    const float* W_da = (const float*)d_in[6];
    const float* b_da = (const float*)d_in[7];
    const float* w_fa = (const float*)d_in[8];
    const float* W_ih = (const float*)d_in[10];
    const float* b_ih = (const float*)d_in[11];
    const float* W_hh = (const float*)d_in[12];
    const float* b_hh = (const float*)d_in[13];
    const float* W_h0 = (const float*)d_in[14];
    const float* b_h0 = (const float*)d_in[15];
    const float* W_c0 = (const float*)d_in[16];
    const float* b_c0 = (const float*)d_in[17];
    const float* W_fb = (const float*)d_in[18];
    const float* b_fb = (const float*)d_in[19];
    const float* W_fc = (const float*)d_in[20];
    const float* b_fc = (const float*)d_in[21];

    float* out       = (float*)d_out;
    float* out_alpha = out + (size_t)Bv * Tv * Vv;

    void* p;
    float *att1, *mean, *h, *c, *hall, *partA;
    cudaGetSymbolAddress(&p, g_att1);  att1  = (float*)p;
    cudaGetSymbolAddress(&p, g_mean);  mean  = (float*)p;
    cudaGetSymbolAddress(&p, g_h);     h     = (float*)p;
    cudaGetSymbolAddress(&p, g_c);     c     = (float*)p;
    cudaGetSymbolAddress(&p, g_hall);  hall  = (float*)p;
    cudaGetSymbolAddress(&p, g_partA); partA = (float*)p;

    cudaFuncSetAttribute(k_steps, cudaFuncAttributeMaxDynamicSharedMemorySize, SMEM_BYTES);

    k_sort<<<1, Bv>>>(lens);
    k_mean<<<dim3(Bv, ENCv / 256), 256>>>(enc);
    // att1 = enc[sort] @ W_ea.T + b_ea  (indirect A rows, sorted output)
    k_bgemm<<<dim3(ATTv / 128, (Bv * Pv) / 128), 256>>>(enc, W_ea, b_ea, att1,
                                                        Bv * Pv, ATTv, ENCv, 2);
    // h0 / c0
    k_sgemm<<<dim3(DECv / 128, KSv), 256>>>(mean, ENCv, DECv, W_h0, partA);
    k_red<<<(Bv * DECv) / 256, 256>>>(h, b_h0, DECv);
    k_sgemm<<<dim3(DECv / 128, KSv), 256>>>(mean, ENCv, DECv, W_c0, partA);
    k_red<<<(Bv * DECv) / 256, 256>>>(c, b_c0, DECv);

    // full recurrence in one persistent kernel
    k_steps<<<NBv, NTv, SMEM_BYTES>>>(enc, caps, embW,
                                      W_da, b_da, W_fb, b_fb, w_fa,
                                      W_ih, b_ih, W_hh, b_hh, out_alpha);

    // predictions: (T*B) x V GEMM with mask+scatter epilogue
    k_bgemm<<<dim3(Vv / 128, (Tv * Bv) / 128), 256>>>(hall, W_fc, b_fc, out,
                                                      Tv * Bv, Vv, DECv, 1);
}

// round 6
// speedup vs baseline: 1.6355x; 1.6355x over previous
#include <cuda_runtime.h>
#include <cstdint>
#include <math.h>

#define Bv   32
#define Pv   196
#define ENCv 2048
#define DECv 512
#define EMBv 512
#define ATTv 512
#define Vv   32000
#define Lv   21
#define Tv   20
#define KSv  8

// ---------------- scratch (static device globals; no allocations) ----------------
__device__ float g_enc_s[(size_t)Bv * Pv * ENCv];   // sorted encoder  (51.4 MB)
__device__ float g_att1 [(size_t)Bv * Pv * ATTv];   // att1            (12.8 MB)
__device__ float g_mean [Bv * ENCv];
__device__ float g_h    [Bv * DECv];
__device__ float g_c    [Bv * DECv];
__device__ float g_att2 [Bv * ATTv];
__device__ float g_gate [Bv * ENCv];
__device__ float g_e    [Bv * Pv];
__device__ float g_alpha[Bv * Pv];
__device__ float g_awe  [Bv * ENCv];
__device__ float g_xh   [Bv * 3072];                 // [emb | gate*awe | h]
__device__ float g_hall [(size_t)Tv * Bv * DECv];    // all h_new, (t,b,d)
__device__ float g_partA[(size_t)KSv * Bv * 2560];   // split-K partials A
__device__ float g_partB[(size_t)KSv * Bv * 2048];   // split-K partials B
__device__ int   g_sort  [Bv];
__device__ int   g_declen[Bv];

// ---------------- small helpers ----------------
__device__ __forceinline__ float sigmf(float x){ return 1.0f / (1.0f + expf(-x)); }

__device__ __forceinline__ uint32_t f2tf32(float x){
    uint32_t r; asm("cvt.rna.tf32.f32 %0, %1;" : "=r"(r) : "f"(x)); return r;
}

#define CP16(dst, src) asm volatile("cp.async.cg.shared.global [%0], [%1], 16;\n" :: "r"(dst), "l"(src))
#define CP_COMMIT()    asm volatile("cp.async.commit_group;\n")
#define CP_WAIT0()     asm volatile("cp.async.wait_group 0;\n")

// stable descending argsort of lengths (matches jnp.argsort(-lens))
__global__ void k_sort(const int* __restrict__ lens)
{
    __shared__ int s[Bv];
    int b = threadIdx.x;
    s[b] = lens[b];
    __syncthreads();
    int my = s[b], rank = 0;
    for (int j = 0; j < Bv; j++) {
        int lj = s[j];
        rank += (lj > my) || (lj == my && j < b);
    }
    g_sort[rank]   = b;
    g_declen[rank] = my - 1;
}

// gather sorted encoder + per-(b,e) mean over P
__global__ void k_gather(const float* __restrict__ enc)
{
    int b = blockIdx.x;
    int e = blockIdx.y * 256 + threadIdx.x;
    int src = g_sort[b];
    const float* in = enc + (size_t)src * Pv * ENCv + e;
    float* o = g_enc_s + (size_t)b * Pv * ENCv + e;
    float s = 0.f;
    #pragma unroll 4
    for (int p = 0; p < Pv; p++) {
        float v = in[(size_t)p * ENCv];
        o[(size_t)p * ENCv] = v;
        s += v;
    }
    g_mean[b * ENCv + e] = s * (1.0f / (float)Pv);
}

// ================= tf32 tensor-core GEMM =================
// C[m,n] = sum_k A[m,k]*W[n,k] + bias[n]
// block tile 128x128, BK=16, 256 threads (8 warps of 64x32), cp.async double buffer.
// Requires M%128==0, N%128==0, K%16==0.
// mode 0: plain store C[m*N+n]
// mode 1: preds epilogue: m=(t*32+b) -> out[b*T*V + t*V + n], zero if t >= declen[b]
#define TSTR 20   // smem row stride in floats (pad: conflict-free frag loads, 16B-aligned)

__global__ void __launch_bounds__(256) k_tgemm(
    const float* __restrict__ A, const float* __restrict__ W,
    const float* __restrict__ bias, float* __restrict__ C,
    int M, int N, int K, int mode)
{
    __shared__ float As[2][128 * TSTR];
    __shared__ float Ws[2][128 * TSTR];

    const int tid  = threadIdx.x;
    const int lane = tid & 31;
    const int wid  = tid >> 5;
    const int wm   = wid >> 2;          // 0..1  (64-row slab)
    const int wn   = wid & 3;           // 0..3  (32-col slab)
    const int m0   = blockIdx.y * 128;
    const int n0   = blockIdx.x * 128;

    // loader coords: this thread copies float4 #tid and #(tid+256) of the 512 per tile
    const int r0l = tid >> 2,          q0l = (tid & 3);
    const int r1l = (tid + 256) >> 2,  q1l = ((tid + 256) & 3);

    uint32_t sA = (uint32_t)__cvta_generic_to_shared(&As[0][0]);
    uint32_t sW = (uint32_t)__cvta_generic_to_shared(&Ws[0][0]);
    const uint32_t bufSz = 128 * TSTR * 4;

    const float* Ab = A + (size_t)m0 * K;
    const float* Wb = W + (size_t)n0 * K;

    float acc[4][4][4];
    #pragma unroll
    for (int i = 0; i < 4; i++)
        #pragma unroll
        for (int j = 0; j < 4; j++)
            #pragma unroll
            for (int v = 0; v < 4; v++) acc[i][j][v] = 0.f;

    const int nk = K >> 4;

    // prologue: load tile 0 into buf 0
    {
        CP16(sA + (r0l * TSTR + q0l * 4) * 4, Ab + (size_t)r0l * K + q0l * 4);
        CP16(sA + (r1l * TSTR + q1l * 4) * 4, Ab + (size_t)r1l * K + q1l * 4);
        CP16(sW + (r0l * TSTR + q0l * 4) * 4, Wb + (size_t)r0l * K + q0l * 4);
        CP16(sW + (r1l * TSTR + q1l * 4) * 4, Wb + (size_t)r1l * K + q1l * 4);
        CP_COMMIT();
    }

    for (int kt = 0; kt < nk; kt++) {
        CP_WAIT0();
        __syncthreads();
        int buf = kt & 1;
        if (kt + 1 < nk) {
            int nb = buf ^ 1;
            int kn = (kt + 1) << 4;
            CP16(sA + nb * bufSz + (r0l * TSTR + q0l * 4) * 4, Ab + (size_t)r0l * K + kn + q0l * 4);
            CP16(sA + nb * bufSz + (r1l * TSTR + q1l * 4) * 4, Ab + (size_t)r1l * K + kn + q1l * 4);
            CP16(sW + nb * bufSz + (r0l * TSTR + q0l * 4) * 4, Wb + (size_t)r0l * K + kn + q0l * 4);
            CP16(sW + nb * bufSz + (r1l * TSTR + q1l * 4) * 4, Wb + (size_t)r1l * K + kn + q1l * 4);
            CP_COMMIT();
        }

        const float* a_s = As[buf];
        const float* w_s = Ws[buf];

        #pragma unroll
        for (int ks = 0; ks < 2; ks++) {
            int kk = ks * 8;
            uint32_t af[4][4], bf[4][2];
            #pragma unroll
            for (int mt = 0; mt < 4; mt++) {
                int r  = wm * 64 + mt * 16 + (lane >> 2);
                int cA = kk + (lane & 3);
                af[mt][0] = f2tf32(a_s[r * TSTR + cA]);
                af[mt][1] = f2tf32(a_s[(r + 8) * TSTR + cA]);
                af[mt][2] = f2tf32(a_s[r * TSTR + cA + 4]);
                af[mt][3] = f2tf32(a_s[(r + 8) * TSTR + cA + 4]);
            }
            #pragma unroll
            for (int nt = 0; nt < 4; nt++) {
                int n  = wn * 32 + nt * 8 + (lane >> 2);
                int kB = kk + (lane & 3);
                bf[nt][0] = f2tf32(w_s[n * TSTR + kB]);
                bf[nt][1] = f2tf32(w_s[n * TSTR + kB + 4]);
            }
            #pragma unroll
            for (int mt = 0; mt < 4; mt++)
                #pragma unroll
                for (int nt = 0; nt < 4; nt++) {
                    asm volatile(
                        "mma.sync.aligned.m16n8k8.row.col.f32.tf32.tf32.f32 "
                        "{%0,%1,%2,%3}, {%4,%5,%6,%7}, {%8,%9}, {%0,%1,%2,%3};\n"
                        : "+f"(acc[mt][nt][0]), "+f"(acc[mt][nt][1]),
                          "+f"(acc[mt][nt][2]), "+f"(acc[mt][nt][3])
                        : "r"(af[mt][0]), "r"(af[mt][1]), "r"(af[mt][2]), "r"(af[mt][3]),
                          "r"(bf[nt][0]), "r"(bf[nt][1]));
                }
        }
    }

    // epilogue
    #pragma unroll
    for (int mt = 0; mt < 4; mt++) {
        int mA = m0 + wm * 64 + mt * 16 + (lane >> 2);
        #pragma unroll
        for (int nt = 0; nt < 4; nt++) {
            int n = n0 + wn * 32 + nt * 8 + (lane & 3) * 2;
            float bz0 = bias[n], bz1 = bias[n + 1];
            float v00 = acc[mt][nt][0] + bz0, v01 = acc[mt][nt][1] + bz1;
            float v10 = acc[mt][nt][2] + bz0, v11 = acc[mt][nt][3] + bz1;
            if (mode == 0) {
                C[(size_t)mA * N + n]           = v00;
                C[(size_t)mA * N + n + 1]       = v01;
                C[(size_t)(mA + 8) * N + n]     = v10;
                C[(size_t)(mA + 8) * N + n + 1] = v11;
            } else {
                int t0 = mA >> 5,      b0 = mA & 31;
                int t1 = (mA + 8) >> 5, b1 = (mA + 8) & 31;
                int ok0 = t0 < g_declen[b0];
                int ok1 = t1 < g_declen[b1];
                size_t o0 = (size_t)b0 * ((size_t)Tv * Vv) + (size_t)t0 * Vv + n;
                size_t o1 = (size_t)b1 * ((size_t)Tv * Vv) + (size_t)t1 * Vv + n;
                C[o0]     = ok0 ? v00 : 0.f;
                C[o0 + 1] = ok0 ? v01 : 0.f;
                C[o1]     = ok1 ? v10 : 0.f;
                C[o1 + 1] = ok1 ? v11 : 0.f;
            }
        }
    }
}

// ---------------- small-M (M=32) split-K GEMM -> partials ----------------
__device__ __forceinline__ const float* w_src(int wmode,
    const float* W1, const float* W2, int n, int k, int K)
{
    if (wmode == 0) return W1 + (size_t)n * K + k;
    if (wmode == 1) return (k < 2560) ? (W1 + (size_t)n * 2560 + k)
                                      : (W2 + (size_t)n * 512 + (k - 2560));
    return (n < 512) ? (W1 + (size_t)n * 512 + k)
                     : (W2 + (size_t)(n - 512) * 512 + k);
}

__global__ void __launch_bounds__(256) k_sgemm(
    const float* __restrict__ A, int K, int N, int wmode,
    const float* __restrict__ W1, const float* __restrict__ W2,
    float* __restrict__ part)
{
    __shared__ float As[16][32];
    __shared__ float Ws[16][128];
    int tid = threadIdx.x;
    int Kc = K / KSv;
    int kbase = blockIdx.y * Kc;
    int n0 = blockIdx.x * 128;
    int tym = tid >> 5, txn = tid & 31;

    float acc[4][4];
    #pragma unroll
    for (int i = 0; i < 4; i++)
        #pragma unroll
        for (int j = 0; j < 4; j++) acc[i][j] = 0.f;

    float4 ra = make_float4(0.f,0.f,0.f,0.f);
    int am = tid >> 2, ac4 = (tid & 3) * 4;
    if (tid < 128) ra = *(const float4*)(A + (size_t)am * K + kbase + ac4);
    int n1 = n0 + (tid >> 2),           kc41 = (tid & 3) * 4;
    int n2 = n0 + ((tid + 256) >> 2),   kc42 = ((tid + 256) & 3) * 4;
    float4 rw0 = *(const float4*)w_src(wmode, W1, W2, n1, kbase + kc41, K);
    float4 rw1 = *(const float4*)w_src(wmode, W1, W2, n2, kbase + kc42, K);

    for (int kb = 0; kb < Kc; kb += 16) {
        __syncthreads();
        if (tid < 128) {
            As[ac4+0][am]=ra.x; As[ac4+1][am]=ra.y; As[ac4+2][am]=ra.z; As[ac4+3][am]=ra.w;
        }
        {
            int nr0 = tid >> 2;
            Ws[kc41+0][nr0]=rw0.x; Ws[kc41+1][nr0]=rw0.y; Ws[kc41+2][nr0]=rw0.z; Ws[kc41+3][nr0]=rw0.w;
            int nr1 = (tid + 256) >> 2;
            Ws[kc42+0][nr1]=rw1.x; Ws[kc42+1][nr1]=rw1.y; Ws[kc42+2][nr1]=rw1.z; Ws[kc42+3][nr1]=rw1.w;
        }
        __syncthreads();
        if (kb + 16 < Kc) {
            int kn = kbase + kb + 16;
            if (tid < 128) ra = *(const float4*)(A + (size_t)am * K + kn + ac4);
            rw0 = *(const float4*)w_src(wmode, W1, W2, n1, kn + kc41, K);
            rw1 = *(const float4*)w_src(wmode, W1, W2, n2, kn + kc42, K);
        }
        #pragma unroll
        for (int k = 0; k < 16; k++) {
            float a[4], w[4];
            *(float4*)a = *(const float4*)&As[k][tym*4];
            *(float4*)w = *(const float4*)&Ws[k][txn*4];
            #pragma unroll
            for (int i = 0; i < 4; i++)
                #pragma unroll
                for (int j = 0; j < 4; j++)
                    acc[i][j] = fmaf(a[i], w[j], acc[i][j]);
        }
    }

    float* pp = part + (size_t)blockIdx.y * Bv * N;
    #pragma unroll
    for (int i = 0; i < 4; i++) {
        int m = tym*4 + i;
        #pragma unroll
        for (int j = 0; j < 4; j++)
            pp[(size_t)m * N + n0 + txn*4 + j] = acc[i][j];
    }
}

// generic split-K reduce (for h0/c0)
__global__ void k_red(float* __restrict__ dest, const float* __restrict__ bias, int N)
{
    int idx = blockIdx.x * 256 + threadIdx.x;
    int b = idx / N, n = idx - b * N;
    float s = bias[n];
    #pragma unroll
    for (int ks = 0; ks < KSv; ks++) s += g_partA[((size_t)ks * Bv + b) * N + n];
    dest[idx] = s;
}

// reduce for att2 (+bias) and gate (sigmoid(+bias))
__global__ void k_redA(const float* __restrict__ b_da, const float* __restrict__ b_fb)
{
    int idx = blockIdx.x * 256 + threadIdx.x;     // 32*2560
    int b = idx / 2560, n = idx - b * 2560;
    float s = 0.f;
    #pragma unroll
    for (int ks = 0; ks < KSv; ks++) s += g_partA[((size_t)ks * Bv + b) * 2560 + n];
    if (n < 512) {
        g_att2[b * 512 + n] = s + b_da[n];
    } else {
        int j = n - 512;
        g_gate[b * ENCv + j] = sigmf(s + b_fb[j]);
    }
}

// e[b,p] = dot( relu(att1[b,p,:] + att2[b,:]), w_fa )  (b_fa dropped: softmax shift-invariant)
__global__ void __launch_bounds__(256) k_e(const float* __restrict__ wfa)
{
    __shared__ float s2[ATTv];
    __shared__ float sw[ATTv];
    int b = blockIdx.x, tid = threadIdx.x;
    for (int i = tid; i < ATTv; i += 256) { s2[i] = g_att2[b * ATTv + i]; sw[i] = wfa[i]; }
    __syncthreads();
    int w = tid >> 5, lane = tid & 31;
    int p = blockIdx.y * 8 + w;
    if (p >= Pv) return;
    const float* a1 = g_att1 + ((size_t)b * Pv + p) * ATTv;
    float s = 0.f;
    #pragma unroll
    for (int it = 0; it < 4; it++) {
        int k = it * 128 + lane * 4;
        float4 v  = *(const float4*)(a1 + k);
        float4 t2 = *(const float4*)(s2 + k);
        float4 wf = *(const float4*)(sw + k);
        s += fmaxf(v.x + t2.x, 0.f) * wf.x + fmaxf(v.y + t2.y, 0.f) * wf.y
           + fmaxf(v.z + t2.z, 0.f) * wf.z + fmaxf(v.w + t2.w, 0.f) * wf.w;
    }
    #pragma unroll
    for (int off = 16; off; off >>= 1) s += __shfl_xor_sync(0xffffffffu, s, off);
    if (lane == 0) g_e[b * Pv + p] = s;
}

// softmax over p, write alpha scratch + masked alphas output
__global__ void __launch_bounds__(256) k_softmax(float* __restrict__ out_alpha, int t)
{
    __shared__ float red[256];
    int b = blockIdx.x, tid = threadIdx.x;
    float v = (tid < Pv) ? g_e[b * Pv + tid] : -3.4e38f;
    red[tid] = v; __syncthreads();
    for (int s = 128; s; s >>= 1) { if (tid < s) red[tid] = fmaxf(red[tid], red[tid + s]); __syncthreads(); }
    float mx = red[0]; __syncthreads();
    float ex = (tid < Pv) ? expf(v - mx) : 0.f;
    red[tid] = ex; __syncthreads();
    for (int s = 128; s; s >>= 1) { if (tid < s) red[tid] += red[tid + s]; __syncthreads(); }
    float inv = 1.0f / red[0];
    if (tid < Pv) {
        float a = ex * inv;
        g_alpha[b * Pv + tid] = a;
        out_alpha[(size_t)b * Tv * Pv + (size_t)t * Pv + tid] = (t < g_declen[b]) ? a : 0.f;
    }
}

// awe[b,e] = sum_p alpha[b,p] * enc_s[b,p,e]
__global__ void k_awe()
{
    __shared__ float sal[Pv];
    int b = blockIdx.x, tid = threadIdx.x;
    if (tid < Pv) sal[tid] = g_alpha[b * Pv + tid];
    __syncthreads();
    int e = blockIdx.y * 256 + tid;
    const float* ep = g_enc_s + (size_t)b * Pv * ENCv + e;
    float s = 0.f;
    #pragma unroll 4
    for (int p = 0; p < Pv; p++) s += sal[p] * ep[(size_t)p * ENCv];
    g_awe[b * ENCv + e] = s;
}

// build xh = [emb_W[cap], gate*awe, h]
__global__ void k_xbuild(const int* __restrict__ caps, const float* __restrict__ embW, int t)
{
    int b = blockIdx.x, tid = threadIdx.x;
    int cap = caps[g_sort[b] * Lv + t];
    const float* er = embW + (size_t)cap * EMBv;
    float* x = g_xh + b * 3072;
    for (int j = tid; j < 3072; j += 256) {
        float v;
        if (j < 512)       v = er[j];
        else if (j < 2560) v = g_gate[b * ENCv + (j - 512)] * g_awe[b * ENCv + (j - 512)];
        else               v = g_h[b * DECv + (j - 2560)];
        x[j] = v;
    }
}

// reduce split-K LSTM gates + pointwise LSTM + masked state update
__global__ void k_lstm(const float* __restrict__ b_ih, const float* __restrict__ b_hh, int t)
{
    int idx = blockIdx.x * 256 + threadIdx.x;   // Bv*DECv = 16384
    int b = idx >> 9, j = idx & 511;
    float gi = b_ih[j]        + b_hh[j];
    float gf = b_ih[512 + j]  + b_hh[512 + j];
    float gg = b_ih[1024 + j] + b_hh[1024 + j];
    float go = b_ih[1536 + j] + b_hh[1536 + j];
    #pragma unroll
    for (int ks = 0; ks < KSv; ks++) {
        const float* pp = g_partB + ((size_t)ks * Bv + b) * 2048;
        gi += pp[j]; gf += pp[512 + j]; gg += pp[1024 + j]; go += pp[1536 + j];
    }
    float cn = sigmf(gf) * g_c[idx] + sigmf(gi) * tanhf(gg);
    float hn = sigmf(go) * tanhf(cn);
    g_hall[((size_t)t * Bv + b) * DECv + j] = hn;
    if (t < g_declen[b]) { g_h[idx] = hn; g_c[idx] = cn; }
}

// ---------------- host launcher ----------------
extern "C" void kernel_launch(void* const* d_in, const int* in_sizes, int n_in,
                              void* d_out, int out_size)
{
    const float* enc  = (const float*)d_in[0];
    const int*   caps = (const int*)  d_in[1];
    const int*   lens = (const int*)  d_in[2];
    const float* embW = (const float*)d_in[3];
    const float* W_ea = (const float*)d_in[4];
    const float* b_ea = (const float*)d_in[5];
    const float* W_da = (const float*)d_in[6];
    const float* b_da = (const float*)d_in[7];
    const float* w_fa = (const float*)d_in[8];
    // d_in[9] = b_fa (unused: softmax shift-invariant)
    const float* W_ih = (const float*)d_in[10];
    const float* b_ih = (const float*)d_in[11];
    const float* W_hh = (const float*)d_in[12];
    const float* b_hh = (const float*)d_in[13];
    const float* W_h0 = (const float*)d_in[14];
    const float* b_h0 = (const float*)d_in[15];
    const float* W_c0 = (const float*)d_in[16];
    const float* b_c0 = (const float*)d_in[17];
    const float* W_fb = (const float*)d_in[18];
    const float* b_fb = (const float*)d_in[19];
    const float* W_fc = (const float*)d_in[20];
    const float* b_fc = (const float*)d_in[21];

    float* out       = (float*)d_out;
    float* out_alpha = out + (size_t)Bv * Tv * Vv;

    void* p;
    float *enc_s, *att1, *mean, *h, *c, *xh, *hall, *partA, *partB;
    cudaGetSymbolAddress(&p, g_enc_s); enc_s = (float*)p;
    cudaGetSymbolAddress(&p, g_att1);  att1  = (float*)p;
    cudaGetSymbolAddress(&p, g_mean);  mean  = (float*)p;
    cudaGetSymbolAddress(&p, g_h);     h     = (float*)p;
    cudaGetSymbolAddress(&p, g_c);     c     = (float*)p;
    cudaGetSymbolAddress(&p, g_xh);    xh    = (float*)p;
    cudaGetSymbolAddress(&p, g_hall);  hall  = (float*)p;
    cudaGetSymbolAddress(&p, g_partA); partA = (float*)p;
    cudaGetSymbolAddress(&p, g_partB); partB = (float*)p;

    // setup
    k_sort<<<1, Bv>>>(lens);
    k_gather<<<dim3(Bv, ENCv / 256), 256>>>(enc);
    // att1 = enc_s @ W_ea.T + b_ea     (6272 x 512, K=2048)  [tf32 tensor cores]
    k_tgemm<<<dim3(ATTv / 128, (Bv * Pv) / 128), 256>>>(enc_s, W_ea, b_ea, att1,
                                                        Bv * Pv, ATTv, ENCv, 0);
    // h0, c0
    k_sgemm<<<dim3(DECv / 128, KSv), 256>>>(mean, ENCv, DECv, 0, W_h0, nullptr, partA);
    k_red<<<(Bv * DECv) / 256, 256>>>(h, b_h0, DECv);
    k_sgemm<<<dim3(DECv / 128, KSv), 256>>>(mean, ENCv, DECv, 0, W_c0, nullptr, partA);
    k_red<<<(Bv * DECv) / 256, 256>>>(c, b_c0, DECv);

    for (int t = 0; t < Tv; t++) {
        // att2 (512) + gate (2048) fused GEMM from h, K=512
        k_sgemm<<<dim3(2560 / 128, KSv), 256>>>(h, DECv, 2560, 2, W_da, W_fb, partA);
        k_redA<<<(Bv * 2560) / 256, 256>>>(b_da, b_fb);
        // attention energies + softmax + awe
        k_e<<<dim3(Bv, 25), 256>>>(w_fa);
        k_softmax<<<Bv, 256>>>(out_alpha, t);
        k_awe<<<dim3(Bv, ENCv / 256), 256>>>();
        // LSTM input build + fused [x|h] GEMM, K=3072
        k_xbuild<<<Bv, 256>>>(caps, embW, t);
        k_sgemm<<<dim3(2048 / 128, KSv), 256>>>(xh, 3072, 2048, 1, W_ih, W_hh, partB);
        k_lstm<<<(Bv * DECv) / 256, 256>>>(b_ih, b_hh, t);
    }

    // predictions: (T*B) x V GEMM with mask+scatter epilogue  [tf32 tensor cores]
    k_tgemm<<<dim3(Vv / 128, (Tv * Bv) / 128), 256>>>(hall, W_fc, b_fc, out,
                                                      Tv * Bv, Vv, DECv, 1);
}

// round 9
// speedup vs baseline: 1.7181x; 1.0505x over previous
#include <cuda_runtime.h>
#include <cstdint>
#include <math.h>

#define Bv   32
#define Pv   196
#define ENCv 2048
#define DECv 512
#define EMBv 512
#define ATTv 512
#define Vv   32000
#define Lv   21
#define Tv   20
#define KSv  8

// ---------------- scratch ----------------
__device__ float g_att1 [(size_t)Bv * Pv * ATTv];    // 12.8 MB (sorted order)
__device__ float g_mean [Bv * ENCv];
__device__ float g_h    [Bv * DECv];
__device__ float g_c    [Bv * DECv];
__device__ float g_e    [Bv * Pv];
__device__ float g_x    [Bv * 2048];                 // gate*awe
__device__ float g_hall [(size_t)Tv * Bv * DECv];
__device__ float g_embA [(size_t)Tv * Bv * EMBv];    // gathered embeddings
__device__ float g_gemb [(size_t)Tv * Bv * 2048];    // emb @ W_ih[:, :512].T
__device__ float g_zero [2048];                      // stays zero (bias for Gemb)
__device__ float g_partA[(size_t)KSv * Bv * 4608];   // GEMM1 partials (att2|gate|WhhH)
__device__ float g_partB[(size_t)16 * Bv * 2048];    // GEMM2 partials (Wih mid)
__device__ int   g_sort  [Bv];
__device__ int   g_declen[Bv];

__device__ __forceinline__ float sigmf(float x){ return 1.0f / (1.0f + expf(-x)); }

__device__ __forceinline__ uint32_t f2tf32(float x){
    uint32_t r; asm("cvt.rna.tf32.f32 %0, %1;" : "=r"(r) : "f"(x)); return r;
}

#define CP16(dst, src) asm volatile("cp.async.cg.shared.global [%0], [%1], 16;\n" :: "r"(dst), "l"(src))
#define CP_COMMIT()    asm volatile("cp.async.commit_group;\n")
#define CP_WAIT0()     asm volatile("cp.async.wait_group 0;\n")

// ---------------- setup kernels ----------------
__global__ void k_sort(const int* __restrict__ lens)
{
    __shared__ int s[Bv];
    int b = threadIdx.x;
    s[b] = lens[b];
    __syncthreads();
    int my = s[b], rank = 0;
    for (int j = 0; j < Bv; j++) {
        int lj = s[j];
        rank += (lj > my) || (lj == my && j < b);
    }
    g_sort[rank]   = b;
    g_declen[rank] = my - 1;
}

__global__ void k_mean(const float* __restrict__ enc)
{
    int b = blockIdx.x;
    int e = blockIdx.y * 256 + threadIdx.x;
    int src = g_sort[b];
    const float* in = enc + (size_t)src * Pv * ENCv + e;
    float s = 0.f;
    #pragma unroll 4
    for (int p = 0; p < Pv; p++) s += in[(size_t)p * ENCv];
    g_mean[b * ENCv + e] = s * (1.0f / (float)Pv);
}

__global__ void k_embg(const int* __restrict__ caps, const float* __restrict__ embW)
{
    int m = blockIdx.x;            // 0..639  (t*32+b)
    int t = m >> 5, b = m & 31;
    int cap = caps[g_sort[b] * Lv + t];
    const float4* src = (const float4*)(embW + (size_t)cap * EMBv);
    float4* dst = (float4*)(g_embA + (size_t)m * EMBv);
    dst[threadIdx.x] = src[threadIdx.x];   // 128 threads x float4 = 512
}

// ================= tf32 tensor-core GEMM, 128x128 tile =================
// C[m,n] = sum_k A[m,k]*W[n,k] + bias[n].  W row stride = wstride.
// mode 0: plain store (C row stride = N)
// mode 1: preds scatter epilogue: m=(t*32+b) -> out[b*T*V + t*V + n], 0 if t>=declen[b]
// mode 2: plain store, A rows indirected through g_sort (row = b*Pv+p)
#define TSTR 20

__global__ void __launch_bounds__(256) k_tgemm(
    const float* __restrict__ A, const float* __restrict__ W,
    const float* __restrict__ bias, float* __restrict__ C,
    int M, int N, int K, int wstride, int mode)
{
    __shared__ float As[2][128 * TSTR];
    __shared__ float Ws[2][128 * TSTR];

    const int tid  = threadIdx.x;
    const int lane = tid & 31;
    const int wid  = tid >> 5;
    const int wm   = wid >> 2;
    const int wn   = wid & 3;
    const int m0   = blockIdx.y * 128;
    const int n0   = blockIdx.x * 128;

    const int r0l = tid >> 2,          q0l = (tid & 3);
    const int r1l = (tid + 256) >> 2,  q1l = ((tid + 256) & 3);

    int r0g = m0 + r0l, r1g = m0 + r1l;
    if (mode == 2) {
        r0g = g_sort[r0g / Pv] * Pv + (r0g % Pv);
        r1g = g_sort[r1g / Pv] * Pv + (r1g % Pv);
    }
    const float* Ap0 = A + (size_t)r0g * K + q0l * 4;
    const float* Ap1 = A + (size_t)r1g * K + q1l * 4;
    const float* Wp0 = W + (size_t)(n0 + r0l) * wstride + q0l * 4;
    const float* Wp1 = W + (size_t)(n0 + r1l) * wstride + q1l * 4;

    uint32_t sA = (uint32_t)__cvta_generic_to_shared(&As[0][0]);
    uint32_t sW = (uint32_t)__cvta_generic_to_shared(&Ws[0][0]);
    const uint32_t bufSz = 128 * TSTR * 4;

    float acc[4][4][4];
    #pragma unroll
    for (int i = 0; i < 4; i++)
        #pragma unroll
        for (int j = 0; j < 4; j++)
            #pragma unroll
            for (int v = 0; v < 4; v++) acc[i][j][v] = 0.f;

    const int nk = K >> 4;

    CP16(sA + (r0l * TSTR + q0l * 4) * 4, Ap0);
    CP16(sA + (r1l * TSTR + q1l * 4) * 4, Ap1);
    CP16(sW + (r0l * TSTR + q0l * 4) * 4, Wp0);
    CP16(sW + (r1l * TSTR + q1l * 4) * 4, Wp1);
    CP_COMMIT();

    for (int kt = 0; kt < nk; kt++) {
        CP_WAIT0();
        __syncthreads();
        int buf = kt & 1;
        if (kt + 1 < nk) {
            int nb = buf ^ 1;
            int kn = (kt + 1) << 4;
            CP16(sA + nb * bufSz + (r0l * TSTR + q0l * 4) * 4, Ap0 + kn);
            CP16(sA + nb * bufSz + (r1l * TSTR + q1l * 4) * 4, Ap1 + kn);
            CP16(sW + nb * bufSz + (r0l * TSTR + q0l * 4) * 4, Wp0 + kn);
            CP16(sW + nb * bufSz + (r1l * TSTR + q1l * 4) * 4, Wp1 + kn);
            CP_COMMIT();
        }

        const float* a_s = As[buf];
        const float* w_s = Ws[buf];

        #pragma unroll
        for (int ks = 0; ks < 2; ks++) {
            int kk = ks * 8;
            uint32_t af[4][4], bf[4][2];
            #pragma unroll
            for (int mt = 0; mt < 4; mt++) {
                int r  = wm * 64 + mt * 16 + (lane >> 2);
                int cA = kk + (lane & 3);
                af[mt][0] = f2tf32(a_s[r * TSTR + cA]);
                af[mt][1] = f2tf32(a_s[(r + 8) * TSTR + cA]);
                af[mt][2] = f2tf32(a_s[r * TSTR + cA + 4]);
                af[mt][3] = f2tf32(a_s[(r + 8) * TSTR + cA + 4]);
            }
            #pragma unroll
            for (int nt = 0; nt < 4; nt++) {
                int n  = wn * 32 + nt * 8 + (lane >> 2);
                int kB = kk + (lane & 3);
                bf[nt][0] = f2tf32(w_s[n * TSTR + kB]);
                bf[nt][1] = f2tf32(w_s[n * TSTR + kB + 4]);
            }
            #pragma unroll
            for (int mt = 0; mt < 4; mt++)
                #pragma unroll
                for (int nt = 0; nt < 4; nt++) {
                    asm volatile(
                        "mma.sync.aligned.m16n8k8.row.col.f32.tf32.tf32.f32 "
                        "{%0,%1,%2,%3}, {%4,%5,%6,%7}, {%8,%9}, {%0,%1,%2,%3};\n"
                        : "+f"(acc[mt][nt][0]), "+f"(acc[mt][nt][1]),
                          "+f"(acc[mt][nt][2]), "+f"(acc[mt][nt][3])
                        : "r"(af[mt][0]), "r"(af[mt][1]), "r"(af[mt][2]), "r"(af[mt][3]),
                          "r"(bf[nt][0]), "r"(bf[nt][1]));
                }
        }
    }

    #pragma unroll
    for (int mt = 0; mt < 4; mt++) {
        int mA = m0 + wm * 64 + mt * 16 + (lane >> 2);
        #pragma unroll
        for (int nt = 0; nt < 4; nt++) {
            int n = n0 + wn * 32 + nt * 8 + (lane & 3) * 2;
            float bz0 = bias[n], bz1 = bias[n + 1];
            float v00 = acc[mt][nt][0] + bz0, v01 = acc[mt][nt][1] + bz1;
            float v10 = acc[mt][nt][2] + bz0, v11 = acc[mt][nt][3] + bz1;
            if (mode == 1) {
                int t0 = mA >> 5,       b0 = mA & 31;
                int t1 = (mA + 8) >> 5, b1 = (mA + 8) & 31;
                int ok0 = t0 < g_declen[b0];
                int ok1 = t1 < g_declen[b1];
                size_t o0 = (size_t)b0 * ((size_t)Tv * Vv) + (size_t)t0 * Vv + n;
                size_t o1 = (size_t)b1 * ((size_t)Tv * Vv) + (size_t)t1 * Vv + n;
                C[o0]     = ok0 ? v00 : 0.f;
                C[o0 + 1] = ok0 ? v01 : 0.f;
                C[o1]     = ok1 ? v10 : 0.f;
                C[o1 + 1] = ok1 ? v11 : 0.f;
            } else {
                C[(size_t)mA * N + n]           = v00;
                C[(size_t)mA * N + n + 1]       = v01;
                C[(size_t)(mA + 8) * N + n]     = v10;
                C[(size_t)(mA + 8) * N + n + 1] = v11;
            }
        }
    }
}

// ---------------- small-M (M=32) split-K GEMM -> partials ----------------
// wmode 0: W1[n*K + k]
// wmode 3: n<512 -> W_da, n<2560 -> W_fb, else -> W_hh   (all K=512 rows)
// wmode 4: W1 = W_ih, src = W1 + n*2560 + 512 + k        (mid 2048 columns)
__device__ __forceinline__ const float* w_src(int wmode,
    const float* W1, const float* W2, const float* W3, int n, int k, int K)
{
    if (wmode == 0) return W1 + (size_t)n * K + k;
    if (wmode == 3) {
        if (n < 512)  return W1 + (size_t)n * 512 + k;
        if (n < 2560) return W2 + (size_t)(n - 512) * 512 + k;
        return W3 + (size_t)(n - 2560) * 512 + k;
    }
    return W1 + (size_t)n * 2560 + 512 + k;   // wmode 4
}

__global__ void __launch_bounds__(256) k_sgemm(
    const float* __restrict__ A, int K, int N, int wmode,
    const float* __restrict__ W1, const float* __restrict__ W2,
    const float* __restrict__ W3, float* __restrict__ part)
{
    __shared__ float As[16][32];
    __shared__ float Ws[16][128];
    int tid = threadIdx.x;
    int Kc = K / gridDim.y;
    int kbase = blockIdx.y * Kc;
    int n0 = blockIdx.x * 128;
    int tym = tid >> 5, txn = tid & 31;

    float acc[4][4];
    #pragma unroll
    for (int i = 0; i < 4; i++)
        #pragma unroll
        for (int j = 0; j < 4; j++) acc[i][j] = 0.f;

    float4 ra = make_float4(0.f,0.f,0.f,0.f);
    int am = tid >> 2, ac4 = (tid & 3) * 4;
    if (tid < 128) ra = *(const float4*)(A + (size_t)am * K + kbase + ac4);
    int n1 = n0 + (tid >> 2),           kc41 = (tid & 3) * 4;
    int n2 = n0 + ((tid + 256) >> 2),   kc42 = ((tid + 256) & 3) * 4;
    float4 rw0 = *(const float4*)w_src(wmode, W1, W2, W3, n1, kbase + kc41, K);
    float4 rw1 = *(const float4*)w_src(wmode, W1, W2, W3, n2, kbase + kc42, K);

    for (int kb = 0; kb < Kc; kb += 16) {
        __syncthreads();
        if (tid < 128) {
            As[ac4+0][am]=ra.x; As[ac4+1][am]=ra.y; As[ac4+2][am]=ra.z; As[ac4+3][am]=ra.w;
        }
        {
            int nr0 = tid >> 2;
            Ws[kc41+0][nr0]=rw0.x; Ws[kc41+1][nr0]=rw0.y; Ws[kc41+2][nr0]=rw0.z; Ws[kc41+3][nr0]=rw0.w;
            int nr1 = (tid + 256) >> 2;
            Ws[kc42+0][nr1]=rw1.x; Ws[kc42+1][nr1]=rw1.y; Ws[kc42+2][nr1]=rw1.z; Ws[kc42+3][nr1]=rw1.w;
        }
        __syncthreads();
        if (kb + 16 < Kc) {
            int kn = kbase + kb + 16;
            if (tid < 128) ra = *(const float4*)(A + (size_t)am * K + kn + ac4);
            rw0 = *(const float4*)w_src(wmode, W1, W2, W3, n1, kn + kc41, K);
            rw1 = *(const float4*)w_src(wmode, W1, W2, W3, n2, kn + kc42, K);
        }
        #pragma unroll
        for (int k = 0; k < 16; k++) {
            float a[4], w[4];
            *(float4*)a = *(const float4*)&As[k][tym*4];
            *(float4*)w = *(const float4*)&Ws[k][txn*4];
            #pragma unroll
            for (int i = 0; i < 4; i++)
                #pragma unroll
                for (int j = 0; j < 4; j++)
                    acc[i][j] = fmaf(a[i], w[j], acc[i][j]);
        }
    }

    float* pp = part + (size_t)blockIdx.y * Bv * N;
    #pragma unroll
    for (int i = 0; i < 4; i++) {
        int m = tym*4 + i;
        #pragma unroll
        for (int j = 0; j < 4; j++)
            pp[(size_t)m * N + n0 + txn*4 + j] = acc[i][j];
    }
}

// split-K reduce (h0/c0)
__global__ void k_red(float* __restrict__ dest, const float* __restrict__ bias, int N)
{
    int idx = blockIdx.x * 256 + threadIdx.x;
    int b = idx / N, n = idx - b * N;
    float s = bias[n];
    #pragma unroll
    for (int ks = 0; ks < KSv; ks++) s += g_partA[((size_t)ks * Bv + b) * N + n];
    dest[idx] = s;
}

// e[b,p] = dot( relu(att1[b,p,:] + att2[b,:]), w_fa ); att2 reduced inline from GEMM1 partials
__global__ void __launch_bounds__(256) k_e(const float* __restrict__ wfa,
                                           const float* __restrict__ b_da)
{
    __shared__ float s2[ATTv];
    __shared__ float sw[ATTv];
    int b = blockIdx.x, tid = threadIdx.x;
    for (int i = tid; i < ATTv; i += 256) {
        float a = b_da[i];
        #pragma unroll
        for (int ks = 0; ks < 8; ks++) a += g_partA[((size_t)(ks * Bv + b)) * 4608 + i];
        s2[i] = a;
        sw[i] = wfa[i];
    }
    __syncthreads();
    int w = tid >> 5, lane = tid & 31;
    int p = blockIdx.y * 8 + w;
    if (p >= Pv) return;
    const float* a1 = g_att1 + ((size_t)(b * Pv + p)) * ATTv;
    float s = 0.f;
    #pragma unroll
    for (int it = 0; it < 4; it++) {
        int k = it * 128 + lane * 4;
        float4 v  = *(const float4*)(a1 + k);
        float4 t2 = *(const float4*)(s2 + k);
        float4 wf = *(const float4*)(sw + k);
        s += fmaxf(v.x + t2.x, 0.f) * wf.x + fmaxf(v.y + t2.y, 0.f) * wf.y
           + fmaxf(v.z + t2.z, 0.f) * wf.z + fmaxf(v.w + t2.w, 0.f) * wf.w;
    }
    #pragma unroll
    for (int off = 16; off; off >>= 1) s += __shfl_xor_sync(0xffffffffu, s, off);
    if (lane == 0) g_e[b * Pv + p] = s;
}

// fused: softmax(e) + awe chunk + gate reduce/sigmoid + x = gate*awe; q==0 writes alphas
__global__ void __launch_bounds__(256) k_aweS(
    const float* __restrict__ enc, const float* __restrict__ b_fb,
    float* __restrict__ out_alpha, int t)
{
    __shared__ float sal[Pv];
    __shared__ float red[256];
    int b = blockIdx.x, q = blockIdx.y, tid = threadIdx.x;
    float v = (tid < Pv) ? g_e[b * Pv + tid] : -3.4e38f;
    red[tid] = v; __syncthreads();
    for (int s = 128; s; s >>= 1) { if (tid < s) red[tid] = fmaxf(red[tid], red[tid + s]); __syncthreads(); }
    float mx = red[0]; __syncthreads();
    float ex = (tid < Pv) ? expf(v - mx) : 0.f;
    red[tid] = ex; __syncthreads();
    for (int s = 128; s; s >>= 1) { if (tid < s) red[tid] += red[tid + s]; __syncthreads(); }
    float inv = 1.0f / red[0];
    if (tid < Pv) {
        sal[tid] = ex * inv;
        if (q == 0)
            out_alpha[(size_t)b * Tv * Pv + (size_t)t * Pv + tid] =
                (t < g_declen[b]) ? ex * inv : 0.f;
    }
    __syncthreads();

    int e = q * 256 + tid;
    int srcb = g_sort[b];
    const float* ep = enc + (size_t)srcb * Pv * ENCv + e;
    float s = 0.f;
    #pragma unroll 4
    for (int p = 0; p < Pv; p++) s += sal[p] * ep[(size_t)p * ENCv];

    float gsum = b_fb[e];
    #pragma unroll
    for (int ks = 0; ks < 8; ks++) gsum += g_partA[((size_t)(ks * Bv + b)) * 4608 + 512 + e];
    g_x[b * 2048 + e] = sigmf(gsum) * s;
}

// reduce all gate partials + Gemb + biases -> LSTM pointwise + masked state update
__global__ void k_lstm(const float* __restrict__ b_ih, const float* __restrict__ b_hh, int t)
{
    int idx = blockIdx.x * 256 + threadIdx.x;   // 16384
    int b = idx >> 9, j = idx & 511;
    float g4[4];
    #pragma unroll
    for (int g = 0; g < 4; g++) {
        int n = g * 512 + j;
        float s = b_ih[n] + b_hh[n] + g_gemb[((size_t)t * Bv + b) * 2048 + n];
        #pragma unroll
        for (int ks = 0; ks < 16; ks++) s += g_partB[((size_t)(ks * Bv + b)) * 2048 + n];
        #pragma unroll
        for (int ks = 0; ks < 8; ks++)  s += g_partA[((size_t)(ks * Bv + b)) * 4608 + 2560 + n];
        g4[g] = s;
    }
    float cn = sigmf(g4[1]) * g_c[idx] + sigmf(g4[0]) * tanhf(g4[2]);
    float hn = sigmf(g4[3]) * tanhf(cn);
    g_hall[((size_t)t * Bv + b) * DECv + j] = hn;
    if (t < g_declen[b]) { g_h[idx] = hn; g_c[idx] = cn; }
}

// ---------------- host launcher (default stream only) ----------------
extern "C" void kernel_launch(void* const* d_in, const int* in_sizes, int n_in,
                              void* d_out, int out_size)
{
    const float* enc  = (const float*)d_in[0];
    const int*   caps = (const int*)  d_in[1];
    const int*   lens = (const int*)  d_in[2];
    const float* embW = (const float*)d_in[3];
    const float* W_ea = (const float*)d_in[4];
    const float* b_ea = (const float*)d_in[5];
    const float* W_da = (const float*)d_in[6];
    const float* b_da = (const float*)d_in[7];
    const float* w_fa = (const float*)d_in[8];
    const float* W_ih = (const float*)d_in[10];
    const float* b_ih = (const float*)d_in[11];
    const float* W_hh = (const float*)d_in[12];
    const float* b_hh = (const float*)d_in[13];
    const float* W_h0 = (const float*)d_in[14];
    const float* b_h0 = (const float*)d_in[15];
    const float* W_c0 = (const float*)d_in[16];
    const float* b_c0 = (const float*)d_in[17];
    const float* W_fb = (const float*)d_in[18];
    const float* b_fb = (const float*)d_in[19];
    const float* W_fc = (const float*)d_in[20];
    const float* b_fc = (const float*)d_in[21];

    float* out       = (float*)d_out;
    float* out_alpha = out + (size_t)Bv * Tv * Vv;

    void* p;
    float *att1, *mean, *h, *c, *hall, *embA, *gemb, *zero, *partA, *partB, *x;
    cudaGetSymbolAddress(&p, g_att1);  att1  = (float*)p;
    cudaGetSymbolAddress(&p, g_mean);  mean  = (float*)p;
    cudaGetSymbolAddress(&p, g_h);     h     = (float*)p;
    cudaGetSymbolAddress(&p, g_c);     c     = (float*)p;
    cudaGetSymbolAddress(&p, g_hall);  hall  = (float*)p;
    cudaGetSymbolAddress(&p, g_embA);  embA  = (float*)p;
    cudaGetSymbolAddress(&p, g_gemb);  gemb  = (float*)p;
    cudaGetSymbolAddress(&p, g_zero);  zero  = (float*)p;
    cudaGetSymbolAddress(&p, g_partA); partA = (float*)p;
    cudaGetSymbolAddress(&p, g_partB); partB = (float*)p;
    cudaGetSymbolAddress(&p, g_x);     x     = (float*)p;

    // ---- setup ----
    k_sort<<<1, Bv>>>(lens);
    k_mean<<<dim3(Bv, ENCv / 256), 256>>>(enc);
    // att1 = enc[sort] @ W_ea.T + b_ea  (tf32, indirect A rows)
    k_tgemm<<<dim3(ATTv / 128, (Bv * Pv) / 128), 256>>>(enc, W_ea, b_ea, att1,
                                                        Bv * Pv, ATTv, ENCv, ENCv, 2);
    // h0 / c0
    k_sgemm<<<dim3(DECv / 128, KSv), 256>>>(mean, ENCv, DECv, 0, W_h0, nullptr, nullptr, partA);
    k_red<<<(Bv * DECv) / 256, 256>>>(h, b_h0, DECv);
    k_sgemm<<<dim3(DECv / 128, KSv), 256>>>(mean, ENCv, DECv, 0, W_c0, nullptr, nullptr, partA);
    k_red<<<(Bv * DECv) / 256, 256>>>(c, b_c0, DECv);
    // Gemb = emb(caps) @ W_ih[:, :512].T   (tf32, all timesteps at once)
    k_embg<<<Tv * Bv, 128>>>(caps, embW);
    k_tgemm<<<dim3(2048 / 128, (Tv * Bv) / 128), 256>>>(embA, W_ih, zero, gemb,
                                                        Tv * Bv, 2048, EMBv, 2560, 0);

    // ---- recurrence: 5 kernels per step ----
    for (int t = 0; t < Tv; t++) {
        // GEMM1: h -> [att2 | gate | W_hh h], N=4608, K=512
        k_sgemm<<<dim3(4608 / 128, 8), 256>>>(h, DECv, 4608, 3, W_da, W_fb, W_hh, partA);
        k_e<<<dim3(Bv, 25), 256>>>(w_fa, b_da);
        k_aweS<<<dim3(Bv, 8), 256>>>(enc, b_fb, out_alpha, t);
        // GEMM2: (gate*awe) @ W_ih[:, 512:2560].T, N=2048, K=2048
        k_sgemm<<<dim3(2048 / 128, 16), 256>>>(x, 2048, 2048, 4, W_ih, nullptr, nullptr, partB);
        k_lstm<<<(Bv * DECv) / 256, 256>>>(b_ih, b_hh, t);
    }

    // predictions: (T*B) x V tf32 GEMM with mask+scatter epilogue
    k_tgemm<<<dim3(Vv / 128, (Tv * Bv) / 128), 256>>>(hall, W_fc, b_fc, out,
                                                      Tv * Bv, Vv, DECv, DECv, 1);
}

// round 12
// speedup vs baseline: 1.7899x; 1.0418x over previous
#include <cuda_runtime.h>
#include <cstdint>
#include <math.h>

#define Bv   32
#define Pv   196
#define ENCv 2048
#define DECv 512
#define EMBv 512
#define ATTv 512
#define Vv   32000
#define Lv   21
#define Tv   20
#define KS1v 4
#define KS2v 8

// ---------------- scratch ----------------
__device__ float g_att1 [(size_t)Bv * Pv * ATTv];    // 12.8 MB (sorted order)
__device__ float g_mean [Bv * ENCv];
__device__ float g_h    [Bv * DECv];
__device__ float g_c    [Bv * DECv];
__device__ float g_e    [Bv * Pv];
__device__ float g_x    [Bv * 2048];                 // gate*awe
__device__ float g_hall [(size_t)Tv * Bv * DECv];
__device__ float g_embA [(size_t)Tv * Bv * EMBv];    // gathered embeddings
__device__ float g_gemb [(size_t)Tv * Bv * 2048];    // emb @ W_ih[:, :512].T
__device__ float g_zero [2048];                      // stays zero (bias for Gemb)
__device__ float g_partA[(size_t)8 * Bv * 4608];     // GEMM1 / h0c0 partials
__device__ float g_partB[(size_t)KS2v * Bv * 2048];  // GEMM2 partials (Wih mid)
__device__ int   g_sort  [Bv];
__device__ int   g_declen[Bv];

__device__ __forceinline__ float sigmf(float x){ return 1.0f / (1.0f + expf(-x)); }

__device__ __forceinline__ uint32_t f2tf32(float x){
    uint32_t r; asm("cvt.rna.tf32.f32 %0, %1;" : "=r"(r) : "f"(x)); return r;
}

#define CP16(dst, src) asm volatile("cp.async.cg.shared.global [%0], [%1], 16;\n" :: "r"(dst), "l"(src))
#define CP_COMMIT()    asm volatile("cp.async.commit_group;\n")
#define CP_WAIT0()     asm volatile("cp.async.wait_group 0;\n")

// ---------------- setup kernels ----------------
__global__ void k_sort(const int* __restrict__ lens)
{
    __shared__ int s[Bv];
    int b = threadIdx.x;
    s[b] = lens[b];
    __syncthreads();
    int my = s[b], rank = 0;
    for (int j = 0; j < Bv; j++) {
        int lj = s[j];
        rank += (lj > my) || (lj == my && j < b);
    }
    g_sort[rank]   = b;
    g_declen[rank] = my - 1;
}

__global__ void k_mean(const float* __restrict__ enc)
{
    int b = blockIdx.x;
    int e = blockIdx.y * 256 + threadIdx.x;
    int src = g_sort[b];
    const float* in = enc + (size_t)src * Pv * ENCv + e;
    float s = 0.f;
    #pragma unroll 4
    for (int p = 0; p < Pv; p++) s += in[(size_t)p * ENCv];
    g_mean[b * ENCv + e] = s * (1.0f / (float)Pv);
}

__global__ void k_embg(const int* __restrict__ caps, const float* __restrict__ embW)
{
    int m = blockIdx.x;            // 0..639  (t*32+b)
    int t = m >> 5, b = m & 31;
    int cap = caps[g_sort[b] * Lv + t];
    const float4* src = (const float4*)(embW + (size_t)cap * EMBv);
    float4* dst = (float4*)(g_embA + (size_t)m * EMBv);
    dst[threadIdx.x] = src[threadIdx.x];   // 128 threads x float4 = 512
}

// ================= tf32 tensor-core GEMM, 128x128 tile =================
// C[m,n] = sum_k A[m,k]*W[n,k] + bias[n].  W row stride = wstride.
// mode 0: plain store (C row stride = N)
// mode 1: preds scatter epilogue: m=(t*32+b) -> out[b*T*V + t*V + n], 0 if t>=declen[b]
// mode 2: plain store, A rows indirected through g_sort (row = b*Pv+p)
#define TSTR 20

__global__ void __launch_bounds__(256) k_tgemm(
    const float* __restrict__ A, const float* __restrict__ W,
    const float* __restrict__ bias, float* __restrict__ C,
    int M, int N, int K, int wstride, int mode)
{
    __shared__ float As[2][128 * TSTR];
    __shared__ float Ws[2][128 * TSTR];

    const int tid  = threadIdx.x;
    const int lane = tid & 31;
    const int wid  = tid >> 5;
    const int wm   = wid >> 2;
    const int wn   = wid & 3;
    const int m0   = blockIdx.y * 128;
    const int n0   = blockIdx.x * 128;

    const int r0l = tid >> 2,          q0l = (tid & 3);
    const int r1l = (tid + 256) >> 2,  q1l = ((tid + 256) & 3);

    int r0g = m0 + r0l, r1g = m0 + r1l;
    if (mode == 2) {
        r0g = g_sort[r0g / Pv] * Pv + (r0g % Pv);
        r1g = g_sort[r1g / Pv] * Pv + (r1g % Pv);
    }
    const float* Ap0 = A + (size_t)r0g * K + q0l * 4;
    const float* Ap1 = A + (size_t)r1g * K + q1l * 4;
    const float* Wp0 = W + (size_t)(n0 + r0l) * wstride + q0l * 4;
    const float* Wp1 = W + (size_t)(n0 + r1l) * wstride + q1l * 4;

    uint32_t sA = (uint32_t)__cvta_generic_to_shared(&As[0][0]);
    uint32_t sW = (uint32_t)__cvta_generic_to_shared(&Ws[0][0]);
    const uint32_t bufSz = 128 * TSTR * 4;

    float acc[4][4][4];
    #pragma unroll
    for (int i = 0; i < 4; i++)
        #pragma unroll
        for (int j = 0; j < 4; j++)
            #pragma unroll
            for (int v = 0; v < 4; v++) acc[i][j][v] = 0.f;

    const int nk = K >> 4;

    CP16(sA + (r0l * TSTR + q0l * 4) * 4, Ap0);
    CP16(sA + (r1l * TSTR + q1l * 4) * 4, Ap1);
    CP16(sW + (r0l * TSTR + q0l * 4) * 4, Wp0);
    CP16(sW + (r1l * TSTR + q1l * 4) * 4, Wp1);
    CP_COMMIT();

    for (int kt = 0; kt < nk; kt++) {
        CP_WAIT0();
        __syncthreads();
        int buf = kt & 1;
        if (kt + 1 < nk) {
            int nb = buf ^ 1;
            int kn = (kt + 1) << 4;
            CP16(sA + nb * bufSz + (r0l * TSTR + q0l * 4) * 4, Ap0 + kn);
            CP16(sA + nb * bufSz + (r1l * TSTR + q1l * 4) * 4, Ap1 + kn);
            CP16(sW + nb * bufSz + (r0l * TSTR + q0l * 4) * 4, Wp0 + kn);
            CP16(sW + nb * bufSz + (r1l * TSTR + q1l * 4) * 4, Wp1 + kn);
            CP_COMMIT();
        }

        const float* a_s = As[buf];
        const float* w_s = Ws[buf];

        #pragma unroll
        for (int ks = 0; ks < 2; ks++) {
            int kk = ks * 8;
            uint32_t af[4][4], bf[4][2];
            #pragma unroll
            for (int mt = 0; mt < 4; mt++) {
                int r  = wm * 64 + mt * 16 + (lane >> 2);
                int cA = kk + (lane & 3);
                af[mt][0] = f2tf32(a_s[r * TSTR + cA]);
                af[mt][1] = f2tf32(a_s[(r + 8) * TSTR + cA]);
                af[mt][2] = f2tf32(a_s[r * TSTR + cA + 4]);
                af[mt][3] = f2tf32(a_s[(r + 8) * TSTR + cA + 4]);
            }
            #pragma unroll
            for (int nt = 0; nt < 4; nt++) {
                int n  = wn * 32 + nt * 8 + (lane >> 2);
                int kB = kk + (lane & 3);
                bf[nt][0] = f2tf32(w_s[n * TSTR + kB]);
                bf[nt][1] = f2tf32(w_s[n * TSTR + kB + 4]);
            }
            #pragma unroll
            for (int mt = 0; mt < 4; mt++)
                #pragma unroll
                for (int nt = 0; nt < 4; nt++) {
                    asm volatile(
                        "mma.sync.aligned.m16n8k8.row.col.f32.tf32.tf32.f32 "
                        "{%0,%1,%2,%3}, {%4,%5,%6,%7}, {%8,%9}, {%0,%1,%2,%3};\n"
                        : "+f"(acc[mt][nt][0]), "+f"(acc[mt][nt][1]),
                          "+f"(acc[mt][nt][2]), "+f"(acc[mt][nt][3])
                        : "r"(af[mt][0]), "r"(af[mt][1]), "r"(af[mt][2]), "r"(af[mt][3]),
                          "r"(bf[nt][0]), "r"(bf[nt][1]));
                }
        }
    }

    #pragma unroll
    for (int mt = 0; mt < 4; mt++) {
        int mA = m0 + wm * 64 + mt * 16 + (lane >> 2);
        #pragma unroll
        for (int nt = 0; nt < 4; nt++) {
            int n = n0 + wn * 32 + nt * 8 + (lane & 3) * 2;
            float bz0 = bias[n], bz1 = bias[n + 1];
            float v00 = acc[mt][nt][0] + bz0, v01 = acc[mt][nt][1] + bz1;
            float v10 = acc[mt][nt][2] + bz0, v11 = acc[mt][nt][3] + bz1;
            if (mode == 1) {
                int t0 = mA >> 5,       b0 = mA & 31;
                int t1 = (mA + 8) >> 5, b1 = (mA + 8) & 31;
                int ok0 = t0 < g_declen[b0];
                int ok1 = t1 < g_declen[b1];
                size_t o0 = (size_t)b0 * ((size_t)Tv * Vv) + (size_t)t0 * Vv + n;
                size_t o1 = (size_t)b1 * ((size_t)Tv * Vv) + (size_t)t1 * Vv + n;
                C[o0]     = ok0 ? v00 : 0.f;
                C[o0 + 1] = ok0 ? v01 : 0.f;
                C[o1]     = ok1 ? v10 : 0.f;
                C[o1 + 1] = ok1 ? v11 : 0.f;
            } else {
                C[(size_t)mA * N + n]           = v00;
                C[(size_t)mA * N + n + 1]       = v01;
                C[(size_t)(mA + 8) * N + n]     = v10;
                C[(size_t)(mA + 8) * N + n + 1] = v11;
            }
        }
    }
}

// ---------------- small-M (M=32) split-K GEMM -> partials ----------------
// wmode 0: W1[n*K + k]
// wmode 3: n<512 -> W_da, n<2560 -> W_fb, else -> W_hh   (all K=512 rows)
// wmode 4: W1 = W_ih, src = W1 + n*2560 + 512 + k        (mid 2048 columns)
// wmode 5: n<512 -> W_h0[n*2048+k], else -> W_c0[(n-512)*2048+k]
__device__ __forceinline__ const float* w_src(int wmode,
    const float* W1, const float* W2, const float* W3, int n, int k, int K)
{
    if (wmode == 0) return W1 + (size_t)n * K + k;
    if (wmode == 3) {
        if (n < 512)  return W1 + (size_t)n * 512 + k;
        if (n < 2560) return W2 + (size_t)(n - 512) * 512 + k;
        return W3 + (size_t)(n - 2560) * 512 + k;
    }
    if (wmode == 5) {
        return (n < 512) ? (W1 + (size_t)n * 2048 + k)
                         : (W2 + (size_t)(n - 512) * 2048 + k);
    }
    return W1 + (size_t)n * 2560 + 512 + k;   // wmode 4
}

__global__ void __launch_bounds__(256) k_sgemm(
    const float* __restrict__ A, int K, int N, int wmode,
    const float* __restrict__ W1, const float* __restrict__ W2,
    const float* __restrict__ W3, float* __restrict__ part)
{
    __shared__ float As[16][32];
    __shared__ float Ws[16][128];
    int tid = threadIdx.x;
    int Kc = K / gridDim.y;
    int kbase = blockIdx.y * Kc;
    int n0 = blockIdx.x * 128;
    int tym = tid >> 5, txn = tid & 31;

    float acc[4][4];
    #pragma unroll
    for (int i = 0; i < 4; i++)
        #pragma unroll
        for (int j = 0; j < 4; j++) acc[i][j] = 0.f;

    float4 ra = make_float4(0.f,0.f,0.f,0.f);
    int am = tid >> 2, ac4 = (tid & 3) * 4;
    if (tid < 128) ra = *(const float4*)(A + (size_t)am * K + kbase + ac4);
    int n1 = n0 + (tid >> 2),           kc41 = (tid & 3) * 4;
    int n2 = n0 + ((tid + 256) >> 2),   kc42 = ((tid + 256) & 3) * 4;
    float4 rw0 = *(const float4*)w_src(wmode, W1, W2, W3, n1, kbase + kc41, K);
    float4 rw1 = *(const float4*)w_src(wmode, W1, W2, W3, n2, kbase + kc42, K);

    for (int kb = 0; kb < Kc; kb += 16) {
        __syncthreads();
        if (tid < 128) {
            As[ac4+0][am]=ra.x; As[ac4+1][am]=ra.y; As[ac4+2][am]=ra.z; As[ac4+3][am]=ra.w;
        }
        {
            int nr0 = tid >> 2;
            Ws[kc41+0][nr0]=rw0.x; Ws[kc41+1][nr0]=rw0.y; Ws[kc41+2][nr0]=rw0.z; Ws[kc41+3][nr0]=rw0.w;
            int nr1 = (tid + 256) >> 2;
            Ws[kc42+0][nr1]=rw1.x; Ws[kc42+1][nr1]=rw1.y; Ws[kc42+2][nr1]=rw1.z; Ws[kc42+3][nr1]=rw1.w;
        }
        __syncthreads();
        if (kb + 16 < Kc) {
            int kn = kbase + kb + 16;
            if (tid < 128) ra = *(const float4*)(A + (size_t)am * K + kn + ac4);
            rw0 = *(const float4*)w_src(wmode, W1, W2, W3, n1, kn + kc41, K);
            rw1 = *(const float4*)w_src(wmode, W1, W2, W3, n2, kn + kc42, K);
        }
        #pragma unroll
        for (int k = 0; k < 16; k++) {
            float a[4], w[4];
            *(float4*)a = *(const float4*)&As[k][tym*4];
            *(float4*)w = *(const float4*)&Ws[k][txn*4];
            #pragma unroll
            for (int i = 0; i < 4; i++)
                #pragma unroll
                for (int j = 0; j < 4; j++)
                    acc[i][j] = fmaf(a[i], w[j], acc[i][j]);
        }
    }

    float* pp = part + (size_t)blockIdx.y * Bv * N;
    #pragma unroll
    for (int i = 0; i < 4; i++) {
        int m = tym*4 + i;
        #pragma unroll
        for (int j = 0; j < 4; j++)
            pp[(size_t)m * N + n0 + txn*4 + j] = acc[i][j];
    }
}

// fused h0/c0 split-K reduce (N=1024: h | c)
__global__ void k_red2(const float* __restrict__ bh, const float* __restrict__ bc)
{
    int idx = blockIdx.x * 256 + threadIdx.x;   // 32*1024
    int b = idx >> 10, n = idx & 1023;
    float s = 0.f;
    #pragma unroll
    for (int ks = 0; ks < 8; ks++) s += g_partA[((size_t)ks * Bv + b) * 1024 + n];
    if (n < 512) g_h[b * 512 + n]         = s + bh[n];
    else         g_c[b * 512 + (n - 512)] = s + bc[n - 512];
}

// e[b,p] = dot( relu(att1[b,p,:] + att2[b,:]), w_fa ); att2 reduced inline from GEMM1 partials
// grid (Bv, 13), 16 p per block (2 per warp)
__global__ void __launch_bounds__(256) k_e(const float* __restrict__ wfa,
                                           const float* __restrict__ b_da)
{
    __shared__ float s2[ATTv];
    __shared__ float sw[ATTv];
    int b = blockIdx.x, tid = threadIdx.x;
    for (int i = tid; i < ATTv; i += 256) {
        float a = b_da[i];
        #pragma unroll
        for (int ks = 0; ks < KS1v; ks++) a += g_partA[((size_t)(ks * Bv + b)) * 4608 + i];
        s2[i] = a;
        sw[i] = wfa[i];
    }
    __syncthreads();
    int w = tid >> 5, lane = tid & 31;
    #pragma unroll
    for (int i = 0; i < 2; i++) {
        int p = blockIdx.y * 16 + w * 2 + i;
        if (p < Pv) {
            const float* a1 = g_att1 + ((size_t)(b * Pv + p)) * ATTv;
            float s = 0.f;
            #pragma unroll
            for (int it = 0; it < 4; it++) {
                int k = it * 128 + lane * 4;
                float4 v  = *(const float4*)(a1 + k);
                float4 t2 = *(const float4*)(s2 + k);
                float4 wf = *(const float4*)(sw + k);
                s += fmaxf(v.x + t2.x, 0.f) * wf.x + fmaxf(v.y + t2.y, 0.f) * wf.y
                   + fmaxf(v.z + t2.z, 0.f) * wf.z + fmaxf(v.w + t2.w, 0.f) * wf.w;
            }
            #pragma unroll
            for (int off = 16; off; off >>= 1) s += __shfl_xor_sync(0xffffffffu, s, off);
            if (lane == 0) g_e[b * Pv + p] = s;
        }
    }
}

// fused: softmax(e) + awe chunk + gate reduce/sigmoid + x = gate*awe; q==0 writes alphas
__global__ void __launch_bounds__(256) k_aweS(
    const float* __restrict__ enc, const float* __restrict__ b_fb,
    float* __restrict__ out_alpha, int t)
{
    __shared__ float sal[Pv];
    __shared__ float red[256];
    int b = blockIdx.x, q = blockIdx.y, tid = threadIdx.x;
    float v = (tid < Pv) ? g_e[b * Pv + tid] : -3.4e38f;
    red[tid] = v; __syncthreads();
    for (int s = 128; s; s >>= 1) { if (tid < s) red[tid] = fmaxf(red[tid], red[tid + s]); __syncthreads(); }
    float mx = red[0]; __syncthreads();
    float ex = (tid < Pv) ? expf(v - mx) : 0.f;
    red[tid] = ex; __syncthreads();
    for (int s = 128; s; s >>= 1) { if (tid < s) red[tid] += red[tid + s]; __syncthreads(); }
    float inv = 1.0f / red[0];
    if (tid < Pv) {
        sal[tid] = ex * inv;
        if (q == 0)
            out_alpha[(size_t)b * Tv * Pv + (size_t)t * Pv + tid] =
                (t < g_declen[b]) ? ex * inv : 0.f;
    }
    __syncthreads();

    int e = q * 256 + tid;
    int srcb = g_sort[b];
    const float* ep = enc + (size_t)srcb * Pv * ENCv + e;
    float s = 0.f;
    #pragma unroll 4
    for (int p = 0; p < Pv; p++) s += sal[p] * ep[(size_t)p * ENCv];

    float gsum = b_fb[e];
    #pragma unroll
    for (int ks = 0; ks < KS1v; ks++) gsum += g_partA[((size_t)(ks * Bv + b)) * 4608 + 512 + e];
    g_x[b * 2048 + e] = sigmf(gsum) * s;
}

// reduce all gate partials + Gemb + biases -> LSTM pointwise + masked state update
__global__ void k_lstm(const float* __restrict__ b_ih, const float* __restrict__ b_hh, int t)
{
    int idx = blockIdx.x * 256 + threadIdx.x;   // 16384
    int b = idx >> 9, j = idx & 511;
    float g4[4];
    #pragma unroll
    for (int g = 0; g < 4; g++) {
        int n = g * 512 + j;
        float s = b_ih[n] + b_hh[n] + g_gemb[((size_t)t * Bv + b) * 2048 + n];
        #pragma unroll
        for (int ks = 0; ks < KS2v; ks++) s += g_partB[((size_t)(ks * Bv + b)) * 2048 + n];
        #pragma unroll
        for (int ks = 0; ks < KS1v; ks++) s += g_partA[((size_t)(ks * Bv + b)) * 4608 + 2560 + n];
        g4[g] = s;
    }
    float cn = sigmf(g4[1]) * g_c[idx] + sigmf(g4[0]) * tanhf(g4[2]);
    float hn = sigmf(g4[3]) * tanhf(cn);
    g_hall[((size_t)t * Bv + b) * DECv + j] = hn;
    if (t < g_declen[b]) { g_h[idx] = hn; g_c[idx] = cn; }
}

// ---------------- host launcher (default stream only) ----------------
extern "C" void kernel_launch(void* const* d_in, const int* in_sizes, int n_in,
                              void* d_out, int out_size)
{
    const float* enc  = (const float*)d_in[0];
    const int*   caps = (const int*)  d_in[1];
    const int*   lens = (const int*)  d_in[2];
    const float* embW = (const float*)d_in[3];
    const float* W_ea = (const float*)d_in[4];
    const float* b_ea = (const float*)d_in[5];
    const float* W_da = (const float*)d_in[6];
    const float* b_da = (const float*)d_in[7];
    const float* w_fa = (const float*)d_in[8];
    const float* W_ih = (const float*)d_in[10];
    const float* b_ih = (const float*)d_in[11];
    const float* W_hh = (const float*)d_in[12];
    const float* b_hh = (const float*)d_in[13];
    const float* W_h0 = (const float*)d_in[14];
    const float* b_h0 = (const float*)d_in[15];
    const float* W_c0 = (const float*)d_in[16];
    const float* b_c0 = (const float*)d_in[17];
    const float* W_fb = (const float*)d_in[18];
    const float* b_fb = (const float*)d_in[19];
    const float* W_fc = (const float*)d_in[20];
    const float* b_fc = (const float*)d_in[21];

    float* out       = (float*)d_out;
    float* out_alpha = out + (size_t)Bv * Tv * Vv;

    void* p;
    float *att1, *mean, *hall, *embA, *gemb, *zero, *partA, *partB, *x;
    cudaGetSymbolAddress(&p, g_att1);  att1  = (float*)p;
    cudaGetSymbolAddress(&p, g_mean);  mean  = (float*)p;
    cudaGetSymbolAddress(&p, g_hall);  hall  = (float*)p;
    cudaGetSymbolAddress(&p, g_embA);  embA  = (float*)p;
    cudaGetSymbolAddress(&p, g_gemb);  gemb  = (float*)p;
    cudaGetSymbolAddress(&p, g_zero);  zero  = (float*)p;
    cudaGetSymbolAddress(&p, g_partA); partA = (float*)p;
    cudaGetSymbolAddress(&p, g_partB); partB = (float*)p;
    cudaGetSymbolAddress(&p, g_x);     x     = (float*)p;

    float* h;
    cudaGetSymbolAddress(&p, g_h); h = (float*)p;

    // ---- setup ----
    k_sort<<<1, Bv>>>(lens);
    k_mean<<<dim3(Bv, ENCv / 256), 256>>>(enc);
    // att1 = enc[sort] @ W_ea.T + b_ea  (tf32, indirect A rows)
    k_tgemm<<<dim3(ATTv / 128, (Bv * Pv) / 128), 256>>>(enc, W_ea, b_ea, att1,
                                                        Bv * Pv, ATTv, ENCv, ENCv, 2);
    // h0 & c0 fused: N=1024, K=2048, ksplit 8
    k_sgemm<<<dim3(1024 / 128, 8), 256>>>(mean, ENCv, 1024, 5, W_h0, W_c0, nullptr, partA);
    k_red2<<<(Bv * 1024) / 256, 256>>>(b_h0, b_c0);
    // Gemb = emb(caps) @ W_ih[:, :512].T   (tf32, all timesteps at once)
    k_embg<<<Tv * Bv, 128>>>(caps, embW);
    k_tgemm<<<dim3(2048 / 128, (Tv * Bv) / 128), 256>>>(embA, W_ih, zero, gemb,
                                                        Tv * Bv, 2048, EMBv, 2560, 0);

    // ---- recurrence: 5 kernels per step ----
    for (int t = 0; t < Tv; t++) {
        // GEMM1: h -> [att2 | gate | W_hh h], N=4608, K=512, ksplit 4
        k_sgemm<<<dim3(4608 / 128, KS1v), 256>>>(h, DECv, 4608, 3, W_da, W_fb, W_hh, partA);
        k_e<<<dim3(Bv, 13), 256>>>(w_fa, b_da);
        k_aweS<<<dim3(Bv, 8), 256>>>(enc, b_fb, out_alpha, t);
        // GEMM2: (gate*awe) @ W_ih[:, 512:2560].T, N=2048, K=2048, ksplit 8
        k_sgemm<<<dim3(2048 / 128, KS2v), 256>>>(x, 2048, 2048, 4, W_ih, nullptr, nullptr, partB);
        k_lstm<<<(Bv * DECv) / 256, 256>>>(b_ih, b_hh, t);
    }

    // predictions: (T*B) x V tf32 GEMM with mask+scatter epilogue
    k_tgemm<<<dim3(Vv / 128, (Tv * Bv) / 128), 256>>>(hall, W_fc, b_fc, out,
                                                      Tv * Bv, Vv, DECv, DECv, 1);
}

// round 14
// speedup vs baseline: 1.9789x; 1.1056x over previous
#include <cuda_runtime.h>
#include <cstdint>
#include <math.h>

#define Bv   32
#define Pv   196
#define ENCv 2048
#define DECv 512
#define EMBv 512
#define ATTv 512
#define Vv   32000
#define Lv   21
#define Tv   20
#define KS1v 4
#define KS2v 8

// ---------------- scratch ----------------
__device__ float g_att1 [(size_t)Bv * Pv * ATTv];    // 12.8 MB (sorted order)
__device__ float g_mean [Bv * ENCv];
__device__ float g_h    [Bv * DECv];
__device__ float g_c    [Bv * DECv];
__device__ float g_e    [Bv * Pv];
__device__ float g_x    [Bv * 2048];                 // gate*awe
__device__ float g_hall [(size_t)Tv * Bv * DECv];
__device__ float g_embA [(size_t)Tv * Bv * EMBv];    // gathered embeddings
__device__ float g_gemb [(size_t)Tv * Bv * 2048];    // emb @ W_ih[:, :512].T
__device__ float g_zero [2048];                      // stays zero (bias for Gemb)
__device__ float g_partA[(size_t)8 * Bv * 4608];     // GEMM1 / h0c0 partials
__device__ float g_partB[(size_t)KS2v * Bv * 2048];  // GEMM2 partials (Wih mid)
__device__ int   g_sort  [Bv];
__device__ int   g_declen[Bv];

__device__ __forceinline__ float sigmf(float x){ return 1.0f / (1.0f + expf(-x)); }

__device__ __forceinline__ uint32_t f2tf32(float x){
    uint32_t r; asm("cvt.rna.tf32.f32 %0, %1;" : "=r"(r) : "f"(x)); return r;
}

#define CP16(dst, src) asm volatile("cp.async.cg.shared.global [%0], [%1], 16;\n" :: "r"(dst), "l"(src))
#define CP_COMMIT()    asm volatile("cp.async.commit_group;\n")
#define CP_WAIT0()     asm volatile("cp.async.wait_group 0;\n")

// ---------------- setup kernels ----------------
__global__ void k_sort(const int* __restrict__ lens)
{
    __shared__ int s[Bv];
    int b = threadIdx.x;
    s[b] = lens[b];
    __syncthreads();
    int my = s[b], rank = 0;
    for (int j = 0; j < Bv; j++) {
        int lj = s[j];
        rank += (lj > my) || (lj == my && j < b);
    }
    g_sort[rank]   = b;
    g_declen[rank] = my - 1;
}

__global__ void k_mean(const float* __restrict__ enc)
{
    int b = blockIdx.x;
    int e = blockIdx.y * 256 + threadIdx.x;
    int src = g_sort[b];
    const float* in = enc + (size_t)src * Pv * ENCv + e;
    float s = 0.f;
    #pragma unroll 4
    for (int p = 0; p < Pv; p++) s += in[(size_t)p * ENCv];
    g_mean[b * ENCv + e] = s * (1.0f / (float)Pv);
}

__global__ void k_embg(const int* __restrict__ caps, const float* __restrict__ embW)
{
    int m = blockIdx.x;            // 0..639  (t*32+b)
    int t = m >> 5, b = m & 31;
    int cap = caps[g_sort[b] * Lv + t];
    const float4* src = (const float4*)(embW + (size_t)cap * EMBv);
    float4* dst = (float4*)(g_embA + (size_t)m * EMBv);
    dst[threadIdx.x] = src[threadIdx.x];   // 128 threads x float4 = 512
}

// ================= tf32 tensor-core GEMM, 128x128 tile =================
// C[m,n] = sum_k A[m,k]*W[n,k] + bias[n].  W row stride = wstride.
// mode 0: plain store (C row stride = N)
// mode 1: preds scatter epilogue: m=(t*32+b) -> out[b*T*V + t*V + n], 0 if t>=declen[b]
// mode 2: plain store, A rows indirected through g_sort (row = b*Pv+p)
#define TSTR 20

__global__ void __launch_bounds__(256) k_tgemm(
    const float* __restrict__ A, const float* __restrict__ W,
    const float* __restrict__ bias, float* __restrict__ C,
    int M, int N, int K, int wstride, int mode)
{
    __shared__ float As[2][128 * TSTR];
    __shared__ float Ws[2][128 * TSTR];

    const int tid  = threadIdx.x;
    const int lane = tid & 31;
    const int wid  = tid >> 5;
    const int wm   = wid >> 2;
    const int wn   = wid & 3;
    const int m0   = blockIdx.y * 128;
    const int n0   = blockIdx.x * 128;

    const int r0l = tid >> 2,          q0l = (tid & 3);
    const int r1l = (tid + 256) >> 2,  q1l = ((tid + 256) & 3);

    int r0g = m0 + r0l, r1g = m0 + r1l;
    if (mode == 2) {
        r0g = g_sort[r0g / Pv] * Pv + (r0g % Pv);
        r1g = g_sort[r1g / Pv] * Pv + (r1g % Pv);
    }
    const float* Ap0 = A + (size_t)r0g * K + q0l * 4;
    const float* Ap1 = A + (size_t)r1g * K + q1l * 4;
    const float* Wp0 = W + (size_t)(n0 + r0l) * wstride + q0l * 4;
    const float* Wp1 = W + (size_t)(n0 + r1l) * wstride + q1l * 4;

    uint32_t sA = (uint32_t)__cvta_generic_to_shared(&As[0][0]);
    uint32_t sW = (uint32_t)__cvta_generic_to_shared(&Ws[0][0]);
    const uint32_t bufSz = 128 * TSTR * 4;

    float acc[4][4][4];
    #pragma unroll
    for (int i = 0; i < 4; i++)
        #pragma unroll
        for (int j = 0; j < 4; j++)
            #pragma unroll
            for (int v = 0; v < 4; v++) acc[i][j][v] = 0.f;

    const int nk = K >> 4;

    CP16(sA + (uint32_t)((r0l * TSTR + q0l * 4) * 4), Ap0);
    CP16(sA + (uint32_t)((r1l * TSTR + q1l * 4) * 4), Ap1);
    CP16(sW + (uint32_t)((r0l * TSTR + q0l * 4) * 4), Wp0);
    CP16(sW + (uint32_t)((r1l * TSTR + q1l * 4) * 4), Wp1);
    CP_COMMIT();

    for (int kt = 0; kt < nk; kt++) {
        CP_WAIT0();
        __syncthreads();
        int buf = kt & 1;
        if (kt + 1 < nk) {
            uint32_t nb = (uint32_t)(buf ^ 1) * bufSz;
            int kn = (kt + 1) << 4;
            CP16(sA + nb + (uint32_t)((r0l * TSTR + q0l * 4) * 4), Ap0 + kn);
            CP16(sA + nb + (uint32_t)((r1l * TSTR + q1l * 4) * 4), Ap1 + kn);
            CP16(sW + nb + (uint32_t)((r0l * TSTR + q0l * 4) * 4), Wp0 + kn);
            CP16(sW + nb + (uint32_t)((r1l * TSTR + q1l * 4) * 4), Wp1 + kn);
            CP_COMMIT();
        }

        const float* a_s = As[buf];
        const float* w_s = Ws[buf];

        #pragma unroll
        for (int ks = 0; ks < 2; ks++) {
            int kk = ks * 8;
            uint32_t af[4][4], bf[4][2];
            #pragma unroll
            for (int mt = 0; mt < 4; mt++) {
                int r  = wm * 64 + mt * 16 + (lane >> 2);
                int cA = kk + (lane & 3);
                af[mt][0] = f2tf32(a_s[r * TSTR + cA]);
                af[mt][1] = f2tf32(a_s[(r + 8) * TSTR + cA]);
                af[mt][2] = f2tf32(a_s[r * TSTR + cA + 4]);
                af[mt][3] = f2tf32(a_s[(r + 8) * TSTR + cA + 4]);
            }
            #pragma unroll
            for (int nt = 0; nt < 4; nt++) {
                int n  = wn * 32 + nt * 8 + (lane >> 2);
                int kB = kk + (lane & 3);
                bf[nt][0] = f2tf32(w_s[n * TSTR + kB]);
                bf[nt][1] = f2tf32(w_s[n * TSTR + kB + 4]);
            }
            #pragma unroll
            for (int mt = 0; mt < 4; mt++)
                #pragma unroll
                for (int nt = 0; nt < 4; nt++) {
                    asm volatile(
                        "mma.sync.aligned.m16n8k8.row.col.f32.tf32.tf32.f32 "
                        "{%0,%1,%2,%3}, {%4,%5,%6,%7}, {%8,%9}, {%0,%1,%2,%3};\n"
                        : "+f"(acc[mt][nt][0]), "+f"(acc[mt][nt][1]),
                          "+f"(acc[mt][nt][2]), "+f"(acc[mt][nt][3])
                        : "r"(af[mt][0]), "r"(af[mt][1]), "r"(af[mt][2]), "r"(af[mt][3]),
                          "r"(bf[nt][0]), "r"(bf[nt][1]));
                }
        }
    }

    #pragma unroll
    for (int mt = 0; mt < 4; mt++) {
        int mA = m0 + wm * 64 + mt * 16 + (lane >> 2);
        #pragma unroll
        for (int nt = 0; nt < 4; nt++) {
            int n = n0 + wn * 32 + nt * 8 + (lane & 3) * 2;
            float bz0 = bias[n], bz1 = bias[n + 1];
            float v00 = acc[mt][nt][0] + bz0, v01 = acc[mt][nt][1] + bz1;
            float v10 = acc[mt][nt][2] + bz0, v11 = acc[mt][nt][3] + bz1;
            if (mode == 1) {
                int t0 = mA >> 5,       b0 = mA & 31;
                int t1 = (mA + 8) >> 5, b1 = (mA + 8) & 31;
                int ok0 = t0 < g_declen[b0];
                int ok1 = t1 < g_declen[b1];
                size_t o0 = (size_t)b0 * ((size_t)Tv * Vv) + (size_t)t0 * Vv + n;
                size_t o1 = (size_t)b1 * ((size_t)Tv * Vv) + (size_t)t1 * Vv + n;
                C[o0]     = ok0 ? v00 : 0.f;
                C[o0 + 1] = ok0 ? v01 : 0.f;
                C[o1]     = ok1 ? v10 : 0.f;
                C[o1 + 1] = ok1 ? v11 : 0.f;
            } else {
                C[(size_t)mA * N + n]           = v00;
                C[(size_t)mA * N + n + 1]       = v01;
                C[(size_t)(mA + 8) * N + n]     = v10;
                C[(size_t)(mA + 8) * N + n + 1] = v11;
            }
        }
    }
}

// ---------------- weight source resolver (shared by small-M kernels) ----------------
// wmode 3: n<512 -> W_da, n<2560 -> W_fb, else -> W_hh   (all K=512 rows)
// wmode 4: W1 = W_ih, src = W1 + n*2560 + 512 + k        (mid 2048 columns)
// wmode 5: n<512 -> W_h0[n*2048+k], else -> W_c0[(n-512)*2048+k]
__device__ __forceinline__ const float* w_src(int wmode,
    const float* W1, const float* W2, const float* W3, int n, int k, int K)
{
    if (wmode == 3) {
        if (n < 512)  return W1 + (size_t)n * 512 + k;
        if (n < 2560) return W2 + (size_t)(n - 512) * 512 + k;
        return W3 + (size_t)(n - 2560) * 512 + k;
    }
    if (wmode == 5) {
        return (n < 512) ? (W1 + (size_t)n * 2048 + k)
                         : (W2 + (size_t)(n - 512) * 2048 + k);
    }
    return W1 + (size_t)n * 2560 + 512 + k;   // wmode 4
}

// ============ small-M (M=32) split-K GEMM on tensor cores (3xTF32) ============
// grid (N/128, KS). Per block: 32 x 128 out over K-chunk Kc = K/KS.
// smem [row][k] layout, stride 36 floats (conflict-free fragments, cp.async, no transpose).
#define SBK 32
#define SSTR 36
#define NSTAGE 3
#define SM_A_FLOATS (32 * SSTR)
#define SM_W_FLOATS (128 * SSTR)
#define TS_SMEM ((NSTAGE * (SM_A_FLOATS + SM_W_FLOATS)) * 4)

__global__ void __launch_bounds__(256) k_tsgemm(
    const float* __restrict__ A, int K, int N, int wmode,
    const float* __restrict__ W1, const float* __restrict__ W2,
    const float* __restrict__ W3, float* __restrict__ part)
{
    extern __shared__ float sm[];
    float* sA = sm;
    float* sW = sm + NSTAGE * SM_A_FLOATS;

    const int tid  = threadIdx.x;
    const int lane = tid & 31;
    const int wid  = tid >> 5;
    const int wm   = wid >> 2;     // 0..1 : m half (16 rows)
    const int wn   = wid & 3;      // 0..3 : 32-col slab
    const int n0   = blockIdx.x * 128;
    const int Kc   = K / gridDim.y;
    const int kbase = blockIdx.y * Kc;
    const int nt   = Kc / SBK;

    uint32_t sAu = (uint32_t)__cvta_generic_to_shared(sA);
    uint32_t sWu = (uint32_t)__cvta_generic_to_shared(sW);

    const int ar = tid >> 3, aq = tid & 7;   // A loader: 32 rows x 8 float4
    const uint32_t aOff = (uint32_t)((ar * SSTR + aq * 4) * 4);

    float acc[4][4];
    #pragma unroll
    for (int i = 0; i < 4; i++)
        #pragma unroll
        for (int v = 0; v < 4; v++) acc[i][v] = 0.f;

    // preload NSTAGE-1 tiles
    #pragma unroll
    for (int s = 0; s < NSTAGE - 1; s++) {
        int kb = kbase + s * SBK;
        CP16(sAu + (uint32_t)(s * SM_A_FLOATS * 4) + aOff,
             A + (size_t)ar * K + kb + aq * 4);
        #pragma unroll
        for (int i = 0; i < 4; i++) {
            int idx = tid + i * 256;
            int r = idx >> 3, q = idx & 7;
            CP16(sWu + (uint32_t)((s * SM_W_FLOATS + r * SSTR + q * 4) * 4),
                 w_src(wmode, W1, W2, W3, n0 + r, kb + q * 4, K));
        }
        CP_COMMIT();
    }

    for (int it = 0; it < nt; it++) {
        asm volatile("cp.async.wait_group %0;\n" :: "n"(NSTAGE - 2));
        __syncthreads();

        if (it + NSTAGE - 1 < nt) {
            int s = (it + NSTAGE - 1) % NSTAGE;
            int kb = kbase + (it + NSTAGE - 1) * SBK;
            CP16(sAu + (uint32_t)(s * SM_A_FLOATS * 4) + aOff,
                 A + (size_t)ar * K + kb + aq * 4);
            #pragma unroll
            for (int i = 0; i < 4; i++) {
                int idx = tid + i * 256;
                int r = idx >> 3, q = idx & 7;
                CP16(sWu + (uint32_t)((s * SM_W_FLOATS + r * SSTR + q * 4) * 4),
                     w_src(wmode, W1, W2, W3, n0 + r, kb + q * 4, K));
            }
            CP_COMMIT();
        } else {
            CP_COMMIT();   // keep group count advancing so wait_group drains older groups
        }

        const float* a_s = sA + (it % NSTAGE) * SM_A_FLOATS;
        const float* w_s = sW + (it % NSTAGE) * SM_W_FLOATS;

        #pragma unroll
        for (int kk = 0; kk < 4; kk++) {
            int c = kk * 8 + (lane & 3);
            int r = wm * 16 + (lane >> 2);
            float a0f = a_s[r * SSTR + c];
            float a1f = a_s[(r + 8) * SSTR + c];
            float a2f = a_s[r * SSTR + c + 4];
            float a3f = a_s[(r + 8) * SSTR + c + 4];
            uint32_t ab[4], arr[4];
            ab[0] = f2tf32(a0f); arr[0] = f2tf32(a0f - __uint_as_float(ab[0]));
            ab[1] = f2tf32(a1f); arr[1] = f2tf32(a1f - __uint_as_float(ab[1]));
            ab[2] = f2tf32(a2f); arr[2] = f2tf32(a2f - __uint_as_float(ab[2]));
            ab[3] = f2tf32(a3f); arr[3] = f2tf32(a3f - __uint_as_float(ab[3]));

            #pragma unroll
            for (int ntile = 0; ntile < 4; ntile++) {
                int n  = wn * 32 + ntile * 8 + (lane >> 2);
                int kB = kk * 8 + (lane & 3);
                float b0f = w_s[n * SSTR + kB];
                float b1f = w_s[n * SSTR + kB + 4];
                uint32_t bb[2], br[2];
                bb[0] = f2tf32(b0f); br[0] = f2tf32(b0f - __uint_as_float(bb[0]));
                bb[1] = f2tf32(b1f); br[1] = f2tf32(b1f - __uint_as_float(bb[1]));

                asm volatile(
                    "mma.sync.aligned.m16n8k8.row.col.f32.tf32.tf32.f32 "
                    "{%0,%1,%2,%3}, {%4,%5,%6,%7}, {%8,%9}, {%0,%1,%2,%3};\n"
                    : "+f"(acc[ntile][0]), "+f"(acc[ntile][1]),
                      "+f"(acc[ntile][2]), "+f"(acc[ntile][3])
                    : "r"(ab[0]), "r"(ab[1]), "r"(ab[2]), "r"(ab[3]),
                      "r"(bb[0]), "r"(bb[1]));
                asm volatile(
                    "mma.sync.aligned.m16n8k8.row.col.f32.tf32.tf32.f32 "
                    "{%0,%1,%2,%3}, {%4,%5,%6,%7}, {%8,%9}, {%0,%1,%2,%3};\n"
                    : "+f"(acc[ntile][0]), "+f"(acc[ntile][1]),
                      "+f"(acc[ntile][2]), "+f"(acc[ntile][3])
                    : "r"(arr[0]), "r"(arr[1]), "r"(arr[2]), "r"(arr[3]),
                      "r"(bb[0]), "r"(bb[1]));
                asm volatile(
                    "mma.sync.aligned.m16n8k8.row.col.f32.tf32.tf32.f32 "
                    "{%0,%1,%2,%3}, {%4,%5,%6,%7}, {%8,%9}, {%0,%1,%2,%3};\n"
                    : "+f"(acc[ntile][0]), "+f"(acc[ntile][1]),
                      "+f"(acc[ntile][2]), "+f"(acc[ntile][3])
                    : "r"(ab[0]), "r"(ab[1]), "r"(ab[2]), "r"(ab[3]),
                      "r"(br[0]), "r"(br[1]));
            }
        }
    }

    float* pp = part + (size_t)blockIdx.y * Bv * N;
    int r = wm * 16 + (lane >> 2);
    #pragma unroll
    for (int ntile = 0; ntile < 4; ntile++) {
        int n = n0 + wn * 32 + ntile * 8 + (lane & 3) * 2;
        pp[(size_t)r * N + n]           = acc[ntile][0];
        pp[(size_t)r * N + n + 1]       = acc[ntile][1];
        pp[(size_t)(r + 8) * N + n]     = acc[ntile][2];
        pp[(size_t)(r + 8) * N + n + 1] = acc[ntile][3];
    }
}

// fused h0/c0 split-K reduce (N=1024: h | c)
__global__ void k_red2(const float* __restrict__ bh, const float* __restrict__ bc)
{
    int idx = blockIdx.x * 256 + threadIdx.x;   // 32*1024
    int b = idx >> 10, n = idx & 1023;
    float s = 0.f;
    #pragma unroll
    for (int ks = 0; ks < 8; ks++) s += g_partA[((size_t)ks * Bv + b) * 1024 + n];
    if (n < 512) g_h[b * 512 + n]         = s + bh[n];
    else         g_c[b * 512 + (n - 512)] = s + bc[n - 512];
}

// e[b,p] = dot( relu(att1[b,p,:] + att2[b,:]), w_fa ); att2 reduced inline from GEMM1 partials
// grid (Bv, 13), 16 p per block (2 per warp)
__global__ void __launch_bounds__(256) k_e(const float* __restrict__ wfa,
                                           const float* __restrict__ b_da)
{
    __shared__ float s2[ATTv];
    __shared__ float sw[ATTv];
    int b = blockIdx.x, tid = threadIdx.x;
    for (int i = tid; i < ATTv; i += 256) {
        float a = b_da[i];
        #pragma unroll
        for (int ks = 0; ks < KS1v; ks++) a += g_partA[((size_t)(ks * Bv + b)) * 4608 + i];
        s2[i] = a;
        sw[i] = wfa[i];
    }
    __syncthreads();
    int w = tid >> 5, lane = tid & 31;
    #pragma unroll
    for (int i = 0; i < 2; i++) {
        int p = blockIdx.y * 16 + w * 2 + i;
        if (p < Pv) {
            const float* a1 = g_att1 + ((size_t)(b * Pv + p)) * ATTv;
            float s = 0.f;
            #pragma unroll
            for (int it = 0; it < 4; it++) {
                int k = it * 128 + lane * 4;
                float4 v  = *(const float4*)(a1 + k);
                float4 t2 = *(const float4*)(s2 + k);
                float4 wf = *(const float4*)(sw + k);
                s += fmaxf(v.x + t2.x, 0.f) * wf.x + fmaxf(v.y + t2.y, 0.f) * wf.y
                   + fmaxf(v.z + t2.z, 0.f) * wf.z + fmaxf(v.w + t2.w, 0.f) * wf.w;
            }
            #pragma unroll
            for (int off = 16; off; off >>= 1) s += __shfl_xor_sync(0xffffffffu, s, off);
            if (lane == 0) g_e[b * Pv + p] = s;
        }
    }
}

// fused: softmax(e) + awe chunk + gate reduce/sigmoid + x = gate*awe; q==0 writes alphas
__global__ void __launch_bounds__(256) k_aweS(
    const float* __restrict__ enc, const float* __restrict__ b_fb,
    float* __restrict__ out_alpha, int t)
{
    __shared__ float sal[Pv];
    __shared__ float red[256];
    int b = blockIdx.x, q = blockIdx.y, tid = threadIdx.x;
    float v = (tid < Pv) ? g_e[b * Pv + tid] : -3.4e38f;
    red[tid] = v; __syncthreads();
    for (int s = 128; s; s >>= 1) { if (tid < s) red[tid] = fmaxf(red[tid], red[tid + s]); __syncthreads(); }
    float mx = red[0]; __syncthreads();
    float ex = (tid < Pv) ? expf(v - mx) : 0.f;
    red[tid] = ex; __syncthreads();
    for (int s = 128; s; s >>= 1) { if (tid < s) red[tid] += red[tid + s]; __syncthreads(); }
    float inv = 1.0f / red[0];
    if (tid < Pv) {
        sal[tid] = ex * inv;
        if (q == 0)
            out_alpha[(size_t)b * Tv * Pv + (size_t)t * Pv + tid] =
                (t < g_declen[b]) ? ex * inv : 0.f;
    }
    __syncthreads();

    int e = q * 256 + tid;
    int srcb = g_sort[b];
    const float* ep = enc + (size_t)srcb * Pv * ENCv + e;
    float s = 0.f;
    #pragma unroll 4
    for (int p = 0; p < Pv; p++) s += sal[p] * ep[(size_t)p * ENCv];

    float gsum = b_fb[e];
    #pragma unroll
    for (int ks = 0; ks < KS1v; ks++) gsum += g_partA[((size_t)(ks * Bv + b)) * 4608 + 512 + e];
    g_x[b * 2048 + e] = sigmf(gsum) * s;
}

// reduce all gate partials + Gemb + biases -> LSTM pointwise + masked state update
__global__ void k_lstm(const float* __restrict__ b_ih, const float* __restrict__ b_hh, int t)
{
    int idx = blockIdx.x * 256 + threadIdx.x;   // 16384
    int b = idx >> 9, j = idx & 511;
    float g4[4];
    #pragma unroll
    for (int g = 0; g < 4; g++) {
        int n = g * 512 + j;
        float s = b_ih[n] + b_hh[n] + g_gemb[((size_t)t * Bv + b) * 2048 + n];
        #pragma unroll
        for (int ks = 0; ks < KS2v; ks++) s += g_partB[((size_t)(ks * Bv + b)) * 2048 + n];
        #pragma unroll
        for (int ks = 0; ks < KS1v; ks++) s += g_partA[((size_t)(ks * Bv + b)) * 4608 + 2560 + n];
        g4[g] = s;
    }
    float cn = sigmf(g4[1]) * g_c[idx] + sigmf(g4[0]) * tanhf(g4[2]);
    float hn = sigmf(g4[3]) * tanhf(cn);
    g_hall[((size_t)t * Bv + b) * DECv + j] = hn;
    if (t < g_declen[b]) { g_h[idx] = hn; g_c[idx] = cn; }
}

// ---------------- host launcher (default stream only) ----------------
extern "C" void kernel_launch(void* const* d_in, const int* in_sizes, int n_in,
                              void* d_out, int out_size)
{
    const float* enc  = (const float*)d_in[0];
    const int*   caps = (const int*)  d_in[1];
    const int*   lens = (const int*)  d_in[2];
    const float* embW = (const float*)d_in[3];
    const float* W_ea = (const float*)d_in[4];
    const float* b_ea = (const float*)d_in[5];
    const float* W_da = (const float*)d_in[6];
    const float* b_da = (const float*)d_in[7];
    const float* w_fa = (const float*)d_in[8];
    const float* W_ih = (const float*)d_in[10];
    const float* b_ih = (const float*)d_in[11];
    const float* W_hh = (const float*)d_in[12];
    const float* b_hh = (const float*)d_in[13];
    const float* W_h0 = (const float*)d_in[14];
    const float* b_h0 = (const float*)d_in[15];
    const float* W_c0 = (const float*)d_in[16];
    const float* b_c0 = (const float*)d_in[17];
    const float* W_fb = (const float*)d_in[18];
    const float* b_fb = (const float*)d_in[19];
    const float* W_fc = (const float*)d_in[20];
    const float* b_fc = (const float*)d_in[21];

    float* out       = (float*)d_out;
    float* out_alpha = out + (size_t)Bv * Tv * Vv;

    void* p;
    float *att1, *mean, *hall, *embA, *gemb, *zero, *partA, *partB, *x;
    cudaGetSymbolAddress(&p, g_att1);  att1  = (float*)p;
    cudaGetSymbolAddress(&p, g_mean);  mean  = (float*)p;
    cudaGetSymbolAddress(&p, g_hall);  hall  = (float*)p;
    cudaGetSymbolAddress(&p, g_embA);  embA  = (float*)p;
    cudaGetSymbolAddress(&p, g_gemb);  gemb  = (float*)p;
    cudaGetSymbolAddress(&p, g_zero);  zero  = (float*)p;
    cudaGetSymbolAddress(&p, g_partA); partA = (float*)p;
    cudaGetSymbolAddress(&p, g_partB); partB = (float*)p;
    cudaGetSymbolAddress(&p, g_x);     x     = (float*)p;

    float* h;
    cudaGetSymbolAddress(&p, g_h); h = (float*)p;

    cudaFuncSetAttribute(k_tsgemm, cudaFuncAttributeMaxDynamicSharedMemorySize, TS_SMEM);

    // ---- setup ----
    k_sort<<<1, Bv>>>(lens);
    k_mean<<<dim3(Bv, ENCv / 256), 256>>>(enc);
    // att1 = enc[sort] @ W_ea.T + b_ea  (tf32, indirect A rows)
    k_tgemm<<<dim3(ATTv / 128, (Bv * Pv) / 128), 256>>>(enc, W_ea, b_ea, att1,
                                                        Bv * Pv, ATTv, ENCv, ENCv, 2);
    // h0 & c0 fused: N=1024, K=2048, ksplit 8 (tensor cores, 3xTF32)
    k_tsgemm<<<dim3(1024 / 128, 8), 256, TS_SMEM>>>(mean, ENCv, 1024, 5, W_h0, W_c0, nullptr, partA);
    k_red2<<<(Bv * 1024) / 256, 256>>>(b_h0, b_c0);
    // Gemb = emb(caps) @ W_ih[:, :512].T   (tf32, all timesteps at once)
    k_embg<<<Tv * Bv, 128>>>(caps, embW);
    k_tgemm<<<dim3(2048 / 128, (Tv * Bv) / 128), 256>>>(embA, W_ih, zero, gemb,
                                                        Tv * Bv, 2048, EMBv, 2560, 0);

    // ---- recurrence: 5 kernels per step ----
    for (int t = 0; t < Tv; t++) {
        // GEMM1: h -> [att2 | gate | W_hh h], N=4608, K=512, ksplit 4 (tensor cores)
        k_tsgemm<<<dim3(4608 / 128, KS1v), 256, TS_SMEM>>>(h, DECv, 4608, 3, W_da, W_fb, W_hh, partA);
        k_e<<<dim3(Bv, 13), 256>>>(w_fa, b_da);
        k_aweS<<<dim3(Bv, 8), 256>>>(enc, b_fb, out_alpha, t);
        // GEMM2: (gate*awe) @ W_ih[:, 512:2560].T, N=2048, K=2048, ksplit 8 (tensor cores)
        k_tsgemm<<<dim3(2048 / 128, KS2v), 256, TS_SMEM>>>(x, 2048, 2048, 4, W_ih, nullptr, nullptr, partB);
        k_lstm<<<(Bv * DECv) / 256, 256>>>(b_ih, b_hh, t);
    }

    // predictions: (T*B) x V tf32 GEMM with mask+scatter epilogue
    k_tgemm<<<dim3(Vv / 128, (Tv * Bv) / 128), 256>>>(hall, W_fc, b_fc, out,
                                                      Tv * Bv, Vv, DECv, DECv, 1);
}